// round 1
// baseline (speedup 1.0000x reference)
#include <cuda_runtime.h>
#include <cstdint>

// ============================================================================
// GroupedMultiQueryAttention — algebraic reduction.
//
// The reference's einsum 'gbshq,gbshk->gbhqk' contracts over the SEQUENCE,
// giving a 64x64 gram matrix; the second einsum 'gbhqk,gbshv->gbshv' sums out
// BOTH q and k, so attention = v * sum(softmax rows) = 64 * v exactly.
// Therefore:  out[g] = X[g] @ (Wv[g] @ Weff[g]),
// where Weff folds the 64x scalar and the KV->H head broadcast into Wo.
// ============================================================================

#define NG     8
#define NB     2
#define NSEQ   2048
#define NEMB   1024
#define NKV    4
#define NHD    64
#define NRAT   4
#define KVDIM  (NKV * NHD)          // 256
#define MROWS  (NB * NSEQ)          // 4096 rows per genome

// Scratch (static device globals — no allocation allowed)
__device__ float g_weff [NG * KVDIM * NEMB];   // [8, 256, 1024]  (8 MB)
__device__ float g_wcomb[NG * NEMB * NEMB];    // [8, 1024, 1024] (32 MB)

// ----------------------------------------------------------------------------
// Step 1: Weff[g, kv*64+d, o] = 64 * sum_{r<4} Wo[g, (kv*4+r)*64+d, o]
// ----------------------------------------------------------------------------
__global__ void fold_wo_kernel(const float* __restrict__ Wo) {
    int idx = blockIdx.x * blockDim.x + threadIdx.x;
    if (idx >= NG * KVDIM * NEMB) return;
    int o  = idx % NEMB;
    int c  = (idx / NEMB) % KVDIM;
    int g  = idx / (KVDIM * NEMB);
    int kv = c / NHD;
    int d  = c % NHD;
    const float* wo = Wo + (size_t)g * NEMB * NEMB;
    float s = 0.f;
#pragma unroll
    for (int r = 0; r < NRAT; r++)
        s += wo[(size_t)((kv * NRAT + r) * NHD + d) * NEMB + o];
    g_weff[idx] = 64.0f * s;
}

// ----------------------------------------------------------------------------
// Tiled SGEMM: C[M,N] = A[M,K] @ B[K,N], row-major.
// BM=BN=128, BK=8, 256 threads, 8x8 per thread (split 4+4 rows/cols).
// Requires: M % 128 == 0, N % 128 == 0, K % 8 == 0 (all shapes here satisfy).
// ----------------------------------------------------------------------------
#define BM 128
#define BN 128
#define BKS 8

__device__ __forceinline__ void sgemm_tile(const float* __restrict__ A,
                                           const float* __restrict__ B,
                                           float* __restrict__ C,
                                           int K, int N) {
    __shared__ float As[BKS][BM];
    __shared__ float Bs[BKS][BN];

    const int tid = threadIdx.x;
    const int tx  = tid & 15;      // 0..15 (col groups)
    const int ty  = tid >> 4;      // 0..15 (row groups)
    const int rowBase = blockIdx.y * BM;
    const int colBase = blockIdx.x * BN;

    // global load mapping
    const int a_r = tid >> 1;           // 0..127
    const int a_c = (tid & 1) << 2;     // 0 or 4
    const int b_r = tid >> 5;           // 0..7
    const int b_c = (tid & 31) << 2;    // 0..124

    const float* Aptr = A + (size_t)(rowBase + a_r) * K + a_c;
    const float* Bptr = B + (size_t)b_r * N + colBase + b_c;

    float acc[8][8];
#pragma unroll
    for (int i = 0; i < 8; i++)
#pragma unroll
        for (int j = 0; j < 8; j++) acc[i][j] = 0.f;

    for (int k0 = 0; k0 < K; k0 += BKS) {
        float4 av = *(const float4*)(Aptr + k0);
        float4 bv = *(const float4*)(Bptr + (size_t)k0 * N);
        As[a_c + 0][a_r] = av.x;
        As[a_c + 1][a_r] = av.y;
        As[a_c + 2][a_r] = av.z;
        As[a_c + 3][a_r] = av.w;
        *(float4*)&Bs[b_r][b_c] = bv;
        __syncthreads();

#pragma unroll
        for (int k = 0; k < BKS; k++) {
            float a[8], b[8];
            *(float4*)&a[0] = *(const float4*)&As[k][ty * 4];
            *(float4*)&a[4] = *(const float4*)&As[k][64 + ty * 4];
            *(float4*)&b[0] = *(const float4*)&Bs[k][tx * 4];
            *(float4*)&b[4] = *(const float4*)&Bs[k][64 + tx * 4];
#pragma unroll
            for (int i = 0; i < 8; i++)
#pragma unroll
                for (int j = 0; j < 8; j++)
                    acc[i][j] = fmaf(a[i], b[j], acc[i][j]);
        }
        __syncthreads();
    }

    // epilogue: 2x2 blocks of 4x4, vectorized stores
#pragma unroll
    for (int i2 = 0; i2 < 2; i2++)
#pragma unroll
        for (int i = 0; i < 4; i++) {
            int row = rowBase + i2 * 64 + ty * 4 + i;
#pragma unroll
            for (int j2 = 0; j2 < 2; j2++) {
                float4 v = make_float4(acc[i2 * 4 + i][j2 * 4 + 0],
                                       acc[i2 * 4 + i][j2 * 4 + 1],
                                       acc[i2 * 4 + i][j2 * 4 + 2],
                                       acc[i2 * 4 + i][j2 * 4 + 3]);
                *(float4*)&C[(size_t)row * N + colBase + j2 * 64 + tx * 4] = v;
            }
        }
}

// Step 2: Wcomb[g] = Wv[g] (1024x256) @ Weff[g] (256x1024)
__global__ void __launch_bounds__(256)
sgemm_wcomb_kernel(const float* __restrict__ Wv) {
    const int g = blockIdx.z;
    const float* A = Wv      + (size_t)g * NEMB * KVDIM;
    const float* B = g_weff  + (size_t)g * KVDIM * NEMB;
    float*       C = g_wcomb + (size_t)g * NEMB * NEMB;
    sgemm_tile(A, B, C, /*K=*/KVDIM, /*N=*/NEMB);
}

// Step 3: out[g] = X[g] (4096x1024) @ Wcomb[g] (1024x1024)
__global__ void __launch_bounds__(256)
sgemm_main_kernel(const float* __restrict__ X, float* __restrict__ out) {
    const int g = blockIdx.z;
    const float* A = X       + (size_t)g * MROWS * NEMB;
    const float* B = g_wcomb + (size_t)g * NEMB * NEMB;
    float*       C = out     + (size_t)g * MROWS * NEMB;
    sgemm_tile(A, B, C, /*K=*/NEMB, /*N=*/NEMB);
}

// ----------------------------------------------------------------------------
extern "C" void kernel_launch(void* const* d_in, const int* in_sizes, int n_in,
                              void* d_out, int out_size) {
    const float* tensor = (const float*)d_in[0];  // [8,2,2048,1024]
    // d_in[1] = Wq (unused), d_in[2] = Wk (unused) — algebraically irrelevant
    const float* Wv = (const float*)d_in[3];      // [8,1024,256]
    const float* Wo = (const float*)d_in[4];      // [8,1024,1024]
    float* out = (float*)d_out;                   // [8,2,2048,1024]

    // 1. Fold Wo (broadcast over heads + scalar 64)
    {
        int total = NG * KVDIM * NEMB;
        fold_wo_kernel<<<(total + 255) / 256, 256>>>(Wo);
    }
    // 2. Wcomb = Wv @ Weff
    {
        dim3 grid(NEMB / BN, NEMB / BM, NG);      // (8, 8, 8)
        sgemm_wcomb_kernel<<<grid, 256>>>(Wv);
    }
    // 3. out = X @ Wcomb
    {
        dim3 grid(NEMB / BN, MROWS / BM, NG);     // (8, 32, 8)
        sgemm_main_kernel<<<grid, 256>>>(tensor, out);
    }
}

// round 4
// speedup vs baseline: 2.1121x; 2.1121x over previous
#include <cuda_runtime.h>
#include <cuda_bf16.h>
#include <cstdint>

// ============================================================================
// GroupedMultiQueryAttention — algebraic reduction + HMMA (mma.sync) bf16-split.
//
// attention = 64 * v  (softmax rows sum to 1; q,k are summed out), so
//   out[g] = X[g] @ (Wv[g] @ Weff[g]),  Weff folds 64x + head broadcast of Wo.
// GEMMs: fp32 -> bf16 hi/lo split, A@B ~= Ahi@Bhi + Ahi@Blo + Alo@Bhi.
// NOTE: build target is plain sm_103 (no 'a') — tcgen05 is unavailable; use
// target-portable mma.sync.m16n8k16 / ldmatrix / cp.async instead.
// ============================================================================

#define NG    8
#define NEMB  1024
#define KVDIM 256
#define MROWS 4096
#define NRAT  4
#define NHD   64

// ---------------- static device scratch -------------------------------------
__device__ float g_weff [NG * KVDIM * NEMB];
__device__ float g_wcomb[NG * NEMB * NEMB];
__device__ __nv_bfloat16 g_wvhi[NG * NEMB * KVDIM];
__device__ __nv_bfloat16 g_wvlo[NG * NEMB * KVDIM];
__device__ __nv_bfloat16 g_bthi[NG * NEMB * KVDIM];
__device__ __nv_bfloat16 g_btlo[NG * NEMB * KVDIM];
__device__ __nv_bfloat16 g_bhi [NG * NEMB * NEMB];
__device__ __nv_bfloat16 g_blo [NG * NEMB * NEMB];
__device__ __nv_bfloat16 g_xhi [(size_t)NG * MROWS * NEMB];
__device__ __nv_bfloat16 g_xlo [(size_t)NG * MROWS * NEMB];

// ---------------- PTX helpers (all portable, non-'a' features) --------------
__device__ __forceinline__ uint32_t smem_u32(const void* p) {
    uint32_t a;
    asm("{ .reg .u64 t; cvta.to.shared.u64 t, %1; cvt.u32.u64 %0, t; }" : "=r"(a) : "l"(p));
    return a;
}
__device__ __forceinline__ void cp16(uint32_t dst, const void* src) {
    asm volatile("cp.async.cg.shared.global [%0], [%1], 16;" :: "r"(dst), "l"(src));
}
#define CP_COMMIT() asm volatile("cp.async.commit_group;" ::: "memory")
#define CP_WAIT(n)  asm volatile("cp.async.wait_group %0;" :: "n"(n) : "memory")

__device__ __forceinline__ void ldsm_x4(uint32_t* r, uint32_t addr) {
    asm volatile("ldmatrix.sync.aligned.m8n8.x4.shared.b16 {%0,%1,%2,%3}, [%4];"
                 : "=r"(r[0]), "=r"(r[1]), "=r"(r[2]), "=r"(r[3]) : "r"(addr));
}
__device__ __forceinline__ void ldsm_x2(uint32_t* r, uint32_t addr) {
    asm volatile("ldmatrix.sync.aligned.m8n8.x2.shared.b16 {%0,%1}, [%2];"
                 : "=r"(r[0]), "=r"(r[1]) : "r"(addr));
}
__device__ __forceinline__ void mma16816(float* d, const uint32_t* a, const uint32_t* b) {
    asm volatile("mma.sync.aligned.m16n8k16.row.col.f32.bf16.bf16.f32 "
                 "{%0,%1,%2,%3}, {%4,%5,%6,%7}, {%8,%9}, {%0,%1,%2,%3};"
                 : "+f"(d[0]), "+f"(d[1]), "+f"(d[2]), "+f"(d[3])
                 : "r"(a[0]), "r"(a[1]), "r"(a[2]), "r"(a[3]), "r"(b[0]), "r"(b[1]));
}

// ---------------- GEMM: C[Mg,Ntot] = A[Mg,K] @ B[Ntot,K]^T (split bf16) -----
#define BM 128
#define BN 128
#define BK 32
#define LDT 40                              // padded smem row stride (elems), 80 B
#define HALF_ELEMS (128 * LDT)              // 5120 elems = 10240 B
#define OFF_AHI 0
#define OFF_ALO (HALF_ELEMS * 2)            // byte offsets
#define OFF_BHI (HALF_ELEMS * 4)
#define OFF_BLO (HALF_ELEMS * 6)
#define STAGE_BYTES (HALF_ELEMS * 8)        // 40960
#define SMEM_TOTAL (2 * STAGE_BYTES)        // 81920

__device__ __forceinline__ void load_tile_half(uint32_t dst,
        const __nv_bfloat16* __restrict__ src, int k0, int K, int tid) {
#pragma unroll
    for (int i = 0; i < 2; i++) {
        int op = tid + i * 256;             // 0..511
        int row = op >> 2, c = op & 3;      // 4 x 16B chunks per 64B row
        uint32_t off = (uint32_t)(row * LDT + c * 8) * 2;
        cp16(dst + off, src + (size_t)row * K + k0 + c * 8);
    }
}

__global__ void __launch_bounds__(256, 1)
gemm_hmma_kernel(const __nv_bfloat16* __restrict__ Ahi, const __nv_bfloat16* __restrict__ Alo,
                 const __nv_bfloat16* __restrict__ Bhi, const __nv_bfloat16* __restrict__ Blo,
                 float* __restrict__ C, int K, int Mg, int Ntot) {
    extern __shared__ char smem[];
    const uint32_t sbase = smem_u32(smem);
    const int tid = threadIdx.x, wid = tid >> 5, lid = tid & 31;
    const int g = blockIdx.z;
    const int mBase = blockIdx.y * BM;
    const int nBase = blockIdx.x * BN;

    const __nv_bfloat16* ahi = Ahi + (size_t)g * Mg * K + (size_t)mBase * K;
    const __nv_bfloat16* alo = Alo + (size_t)g * Mg * K + (size_t)mBase * K;
    const __nv_bfloat16* bhi = Bhi + (size_t)g * Ntot * K + (size_t)nBase * K;
    const __nv_bfloat16* blo = Blo + (size_t)g * Ntot * K + (size_t)nBase * K;
    float* c = C + (size_t)g * Mg * Ntot + (size_t)mBase * Ntot + nBase;

    // warp tiling: 2 (m) x 4 (n) warps; warp tile 64 x 32
    const int wm = (wid >> 2) * 64;
    const int wn = (wid & 3) * 32;
    const int lr = lid & 7, ls = lid >> 3;
    // ldmatrix lane address components
    const uint32_t aRow = (uint32_t)((ls & 1) * 8 + lr);
    const uint32_t aK   = (uint32_t)((ls >> 1) * 8);
    const uint32_t bK   = (uint32_t)((ls & 1) * 8);

    float acc[4][4][4];
#pragma unroll
    for (int mt = 0; mt < 4; mt++)
#pragma unroll
        for (int nt = 0; nt < 4; nt++)
#pragma unroll
            for (int q = 0; q < 4; q++) acc[mt][nt][q] = 0.f;

    const int nk = K / BK;

    // prologue
    load_tile_half(sbase + OFF_AHI, ahi, 0, K, tid);
    load_tile_half(sbase + OFF_ALO, alo, 0, K, tid);
    load_tile_half(sbase + OFF_BHI, bhi, 0, K, tid);
    load_tile_half(sbase + OFF_BLO, blo, 0, K, tid);
    CP_COMMIT();

    for (int it = 0; it < nk; ++it) {
        const int s = it & 1;
        if (it + 1 < nk) {
            const uint32_t st1 = sbase + (uint32_t)(s ^ 1) * STAGE_BYTES;
            const int k1 = (it + 1) * BK;
            load_tile_half(st1 + OFF_AHI, ahi, k1, K, tid);
            load_tile_half(st1 + OFF_ALO, alo, k1, K, tid);
            load_tile_half(st1 + OFF_BHI, bhi, k1, K, tid);
            load_tile_half(st1 + OFF_BLO, blo, k1, K, tid);
            CP_COMMIT();
            CP_WAIT(1);
        } else {
            CP_WAIT(0);
        }
        __syncthreads();

        const uint32_t st = sbase + (uint32_t)s * STAGE_BYTES;
#pragma unroll
        for (int kk = 0; kk < BK; kk += 16) {
            uint32_t ah[4][4], al[4][4], bh[4][2], bl[4][2];
#pragma unroll
            for (int mt = 0; mt < 4; mt++) {
                uint32_t ro = (uint32_t)((wm + mt * 16 + aRow) * LDT + kk + aK) * 2;
                ldsm_x4(ah[mt], st + OFF_AHI + ro);
                ldsm_x4(al[mt], st + OFF_ALO + ro);
            }
#pragma unroll
            for (int nt = 0; nt < 4; nt++) {
                uint32_t ro = (uint32_t)((wn + nt * 8 + lr) * LDT + kk + bK) * 2;
                ldsm_x2(bh[nt], st + OFF_BHI + ro);
                ldsm_x2(bl[nt], st + OFF_BLO + ro);
            }
#pragma unroll
            for (int mt = 0; mt < 4; mt++)
#pragma unroll
                for (int nt = 0; nt < 4; nt++) {
                    mma16816(acc[mt][nt], ah[mt], bh[nt]);   // hi*hi
                    mma16816(acc[mt][nt], ah[mt], bl[nt]);   // hi*lo
                    mma16816(acc[mt][nt], al[mt], bh[nt]);   // lo*hi
                }
        }
        __syncthreads();
    }

    // epilogue: fragment layout c0,c1 = (row l/4, col 2(l%4)+{0,1}); c2,c3 row+8
    const int er = lid >> 2, ec = (lid & 3) * 2;
#pragma unroll
    for (int mt = 0; mt < 4; mt++)
#pragma unroll
        for (int nt = 0; nt < 4; nt++) {
            int row = wm + mt * 16 + er;
            int col = wn + nt * 8 + ec;
            *(float2*)&c[(size_t)row * Ntot + col] =
                make_float2(acc[mt][nt][0], acc[mt][nt][1]);
            *(float2*)&c[(size_t)(row + 8) * Ntot + col] =
                make_float2(acc[mt][nt][2], acc[mt][nt][3]);
        }
}

// ---------------- helper kernels --------------------------------------------
__global__ void fold_wo_kernel(const float* __restrict__ Wo) {
    int idx = blockIdx.x * blockDim.x + threadIdx.x;
    if (idx >= NG * KVDIM * NEMB) return;
    int o = idx % NEMB;
    int cc = (idx / NEMB) % KVDIM;
    int g = idx / (KVDIM * NEMB);
    int kv = cc / NHD, d = cc % NHD;
    const float* wo = Wo + (size_t)g * NEMB * NEMB;
    float s = 0.f;
#pragma unroll
    for (int r = 0; r < NRAT; r++)
        s += wo[(size_t)((kv * NRAT + r) * NHD + d) * NEMB + o];
    g_weff[idx] = 64.0f * s;
}

__global__ void split_kernel(const float* __restrict__ in,
                             __nv_bfloat16* __restrict__ hi,
                             __nv_bfloat16* __restrict__ lo, size_t n4) {
    size_t i = (size_t)blockIdx.x * blockDim.x + threadIdx.x;
    if (i >= n4) return;
    float4 v = ((const float4*)in)[i];
    __nv_bfloat16 h0 = __float2bfloat16(v.x), h1 = __float2bfloat16(v.y);
    __nv_bfloat16 h2 = __float2bfloat16(v.z), h3 = __float2bfloat16(v.w);
    __nv_bfloat16 l0 = __float2bfloat16(v.x - __bfloat162float(h0));
    __nv_bfloat16 l1 = __float2bfloat16(v.y - __bfloat162float(h1));
    __nv_bfloat16 l2 = __float2bfloat16(v.z - __bfloat162float(h2));
    __nv_bfloat16 l3 = __float2bfloat16(v.w - __bfloat162float(h3));
    ushort4 hv, lv;
    hv.x = *(unsigned short*)&h0; hv.y = *(unsigned short*)&h1;
    hv.z = *(unsigned short*)&h2; hv.w = *(unsigned short*)&h3;
    lv.x = *(unsigned short*)&l0; lv.y = *(unsigned short*)&l1;
    lv.z = *(unsigned short*)&l2; lv.w = *(unsigned short*)&l3;
    ((ushort4*)hi)[i] = hv;
    ((ushort4*)lo)[i] = lv;
}

__global__ void transpose_split_kernel(const float* __restrict__ in,
                                       __nv_bfloat16* __restrict__ hi,
                                       __nv_bfloat16* __restrict__ lo,
                                       int R, int Cc) {
    __shared__ float t[32][33];
    const int g = blockIdx.z;
    const int cB = blockIdx.x * 32, rB = blockIdx.y * 32;
    const int tx = threadIdx.x, ty = threadIdx.y;
    const float* I = in + (size_t)g * R * Cc;
#pragma unroll
    for (int j = 0; j < 4; j++)
        t[ty + j * 8][tx] = I[(size_t)(rB + ty + j * 8) * Cc + cB + tx];
    __syncthreads();
    __nv_bfloat16* H = hi + (size_t)g * R * Cc;
    __nv_bfloat16* L = lo + (size_t)g * R * Cc;
#pragma unroll
    for (int j = 0; j < 4; j++) {
        float x = t[tx][ty + j * 8];
        __nv_bfloat16 h = __float2bfloat16(x);
        __nv_bfloat16 l = __float2bfloat16(x - __bfloat162float(h));
        size_t o = (size_t)(cB + ty + j * 8) * R + rB + tx;
        H[o] = h; L[o] = l;
    }
}

// ---------------- launch -----------------------------------------------------
extern "C" void kernel_launch(void* const* d_in, const int* in_sizes, int n_in,
                              void* d_out, int out_size) {
    const float* tensor = (const float*)d_in[0];
    const float* Wv = (const float*)d_in[3];
    const float* Wo = (const float*)d_in[4];
    float* out = (float*)d_out;

    static bool attr_done = false;
    if (!attr_done) {
        cudaFuncSetAttribute(gemm_hmma_kernel,
                             cudaFuncAttributeMaxDynamicSharedMemorySize, SMEM_TOTAL);
        attr_done = true;
    }

    __nv_bfloat16 *wvhi, *wvlo, *bthi, *btlo, *bhi, *blo, *xhi, *xlo;
    float *weff, *wcomb;
    cudaGetSymbolAddress((void**)&weff,  g_weff);
    cudaGetSymbolAddress((void**)&wcomb, g_wcomb);
    cudaGetSymbolAddress((void**)&wvhi,  g_wvhi);
    cudaGetSymbolAddress((void**)&wvlo,  g_wvlo);
    cudaGetSymbolAddress((void**)&bthi,  g_bthi);
    cudaGetSymbolAddress((void**)&btlo,  g_btlo);
    cudaGetSymbolAddress((void**)&bhi,   g_bhi);
    cudaGetSymbolAddress((void**)&blo,   g_blo);
    cudaGetSymbolAddress((void**)&xhi,   g_xhi);
    cudaGetSymbolAddress((void**)&xlo,   g_xlo);

    // 1. fold Wo -> Weff fp32 [g][256][1024]
    fold_wo_kernel<<<(NG * KVDIM * NEMB + 255) / 256, 256>>>(Wo);
    // 2. split Wv ([1024][256] K-major)
    {
        size_t n4 = (size_t)NG * NEMB * KVDIM / 4;
        split_kernel<<<(unsigned)((n4 + 255) / 256), 256>>>(Wv, wvhi, wvlo, n4);
    }
    // 3. transpose+split Weff [256][1024] -> [1024][256]
    {
        dim3 grid(NEMB / 32, KVDIM / 32, NG);
        transpose_split_kernel<<<grid, dim3(32, 8)>>>(weff, bthi, btlo, KVDIM, NEMB);
    }
    // 4. GEMM2: Wcomb = Wv @ Weff   (M=N=1024, K=256)
    {
        dim3 grid(NEMB / BN, NEMB / BM, NG);   // (8, 8, 8)
        gemm_hmma_kernel<<<grid, 256, SMEM_TOTAL>>>(wvhi, wvlo, bthi, btlo,
                                                    wcomb, KVDIM, NEMB, NEMB);
    }
    // 5. transpose+split Wcomb [1024][1024] -> B3 [1024][1024]
    {
        dim3 grid(NEMB / 32, NEMB / 32, NG);
        transpose_split_kernel<<<grid, dim3(32, 8)>>>(wcomb, bhi, blo, NEMB, NEMB);
    }
    // 6. split X
    {
        size_t n4 = (size_t)NG * MROWS * NEMB / 4;
        split_kernel<<<(unsigned)((n4 + 255) / 256), 256>>>(tensor, xhi, xlo, n4);
    }
    // 7. GEMM3: out = X @ Wcomb   (M=4096/genome, N=1024, K=1024)
    {
        dim3 grid(NEMB / BN, MROWS / BM, NG);  // (8, 32, 8)
        gemm_hmma_kernel<<<grid, 256, SMEM_TOTAL>>>(xhi, xlo, bhi, blo,
                                                    out, NEMB, MROWS, NEMB);
    }
}

// round 5
// speedup vs baseline: 2.4895x; 1.1787x over previous
#include <cuda_runtime.h>
#include <cuda_bf16.h>
#include <cstdint>

// ============================================================================
// GroupedMultiQueryAttention — algebraic reduction + HMMA (mma.sync) bf16-split.
//
// attention = 64 * v  (softmax rows sum to 1; q,k are summed out), so
//   out[g] = X[g] @ (Wv[g] @ Weff[g]),  Weff folds 64x + head broadcast of Wo.
// GEMMs: fp32 -> bf16 hi/lo split, A@B ~= Ahi@Bhi + Ahi@Blo + Alo@Bhi.
// Round 5: mt-major fragment scheduling + __launch_bounds__(256,2) to drop
// regs <=128 so 2 CTAs/SM fit (was 1 CTA -> occ 12.7%, tensor 39%).
// ============================================================================

#define NG    8
#define NEMB  1024
#define KVDIM 256
#define MROWS 4096
#define NRAT  4
#define NHD   64

// ---------------- static device scratch -------------------------------------
__device__ float g_weff [NG * KVDIM * NEMB];
__device__ float g_wcomb[NG * NEMB * NEMB];
__device__ __nv_bfloat16 g_wvhi[NG * NEMB * KVDIM];
__device__ __nv_bfloat16 g_wvlo[NG * NEMB * KVDIM];
__device__ __nv_bfloat16 g_bthi[NG * NEMB * KVDIM];
__device__ __nv_bfloat16 g_btlo[NG * NEMB * KVDIM];
__device__ __nv_bfloat16 g_bhi [NG * NEMB * NEMB];
__device__ __nv_bfloat16 g_blo [NG * NEMB * NEMB];
__device__ __nv_bfloat16 g_xhi [(size_t)NG * MROWS * NEMB];
__device__ __nv_bfloat16 g_xlo [(size_t)NG * MROWS * NEMB];

// ---------------- PTX helpers ------------------------------------------------
__device__ __forceinline__ uint32_t smem_u32(const void* p) {
    uint32_t a;
    asm("{ .reg .u64 t; cvta.to.shared.u64 t, %1; cvt.u32.u64 %0, t; }" : "=r"(a) : "l"(p));
    return a;
}
__device__ __forceinline__ void cp16(uint32_t dst, const void* src) {
    asm volatile("cp.async.cg.shared.global [%0], [%1], 16;" :: "r"(dst), "l"(src));
}
#define CP_COMMIT() asm volatile("cp.async.commit_group;" ::: "memory")
#define CP_WAIT(n)  asm volatile("cp.async.wait_group %0;" :: "n"(n) : "memory")

__device__ __forceinline__ void ldsm_x4(uint32_t* r, uint32_t addr) {
    asm volatile("ldmatrix.sync.aligned.m8n8.x4.shared.b16 {%0,%1,%2,%3}, [%4];"
                 : "=r"(r[0]), "=r"(r[1]), "=r"(r[2]), "=r"(r[3]) : "r"(addr));
}
__device__ __forceinline__ void ldsm_x2(uint32_t* r, uint32_t addr) {
    asm volatile("ldmatrix.sync.aligned.m8n8.x2.shared.b16 {%0,%1}, [%2];"
                 : "=r"(r[0]), "=r"(r[1]) : "r"(addr));
}
__device__ __forceinline__ void mma16816(float* d, const uint32_t* a, const uint32_t* b) {
    asm volatile("mma.sync.aligned.m16n8k16.row.col.f32.bf16.bf16.f32 "
                 "{%0,%1,%2,%3}, {%4,%5,%6,%7}, {%8,%9}, {%0,%1,%2,%3};"
                 : "+f"(d[0]), "+f"(d[1]), "+f"(d[2]), "+f"(d[3])
                 : "r"(a[0]), "r"(a[1]), "r"(a[2]), "r"(a[3]), "r"(b[0]), "r"(b[1]));
}

// ---------------- GEMM: C[Mg,Ntot] = A[Mg,K] @ B[Ntot,K]^T (split bf16) -----
#define BM 128
#define BN 128
#define BK 32
#define LDT 40                              // padded smem row stride (elems)
#define HALF_ELEMS (128 * LDT)
#define OFF_AHI 0
#define OFF_ALO (HALF_ELEMS * 2)
#define OFF_BHI (HALF_ELEMS * 4)
#define OFF_BLO (HALF_ELEMS * 6)
#define STAGE_BYTES (HALF_ELEMS * 8)        // 40960
#define SMEM_TOTAL (2 * STAGE_BYTES)        // 81920

__device__ __forceinline__ void load_tile_half(uint32_t dst,
        const __nv_bfloat16* __restrict__ src, int k0, int K, int tid) {
#pragma unroll
    for (int i = 0; i < 2; i++) {
        int op = tid + i * 256;
        int row = op >> 2, c = op & 3;
        uint32_t off = (uint32_t)(row * LDT + c * 8) * 2;
        cp16(dst + off, src + (size_t)row * K + k0 + c * 8);
    }
}

__global__ void __launch_bounds__(256, 2)
gemm_hmma_kernel(const __nv_bfloat16* __restrict__ Ahi, const __nv_bfloat16* __restrict__ Alo,
                 const __nv_bfloat16* __restrict__ Bhi, const __nv_bfloat16* __restrict__ Blo,
                 float* __restrict__ C, int K, int Mg, int Ntot) {
    extern __shared__ char smem[];
    const uint32_t sbase = smem_u32(smem);
    const int tid = threadIdx.x, wid = tid >> 5, lid = tid & 31;
    const int g = blockIdx.z;
    const int mBase = blockIdx.y * BM;
    const int nBase = blockIdx.x * BN;

    const __nv_bfloat16* ahi = Ahi + (size_t)g * Mg * K + (size_t)mBase * K;
    const __nv_bfloat16* alo = Alo + (size_t)g * Mg * K + (size_t)mBase * K;
    const __nv_bfloat16* bhi = Bhi + (size_t)g * Ntot * K + (size_t)nBase * K;
    const __nv_bfloat16* blo = Blo + (size_t)g * Ntot * K + (size_t)nBase * K;
    float* c = C + (size_t)g * Mg * Ntot + (size_t)mBase * Ntot + nBase;

    // warp tiling: 2 (m) x 4 (n) warps; warp tile 64 x 32
    const int wm = (wid >> 2) * 64;
    const int wn = (wid & 3) * 32;
    const int lr = lid & 7, ls = lid >> 3;
    const uint32_t aRow = (uint32_t)((ls & 1) * 8 + lr);
    const uint32_t aK   = (uint32_t)((ls >> 1) * 8);
    const uint32_t bK   = (uint32_t)((ls & 1) * 8);

    float acc[4][4][4];
#pragma unroll
    for (int mt = 0; mt < 4; mt++)
#pragma unroll
        for (int nt = 0; nt < 4; nt++)
#pragma unroll
            for (int q = 0; q < 4; q++) acc[mt][nt][q] = 0.f;

    const int nk = K / BK;

    load_tile_half(sbase + OFF_AHI, ahi, 0, K, tid);
    load_tile_half(sbase + OFF_ALO, alo, 0, K, tid);
    load_tile_half(sbase + OFF_BHI, bhi, 0, K, tid);
    load_tile_half(sbase + OFF_BLO, blo, 0, K, tid);
    CP_COMMIT();

    for (int it = 0; it < nk; ++it) {
        const int s = it & 1;
        if (it + 1 < nk) {
            const uint32_t st1 = sbase + (uint32_t)(s ^ 1) * STAGE_BYTES;
            const int k1 = (it + 1) * BK;
            load_tile_half(st1 + OFF_AHI, ahi, k1, K, tid);
            load_tile_half(st1 + OFF_ALO, alo, k1, K, tid);
            load_tile_half(st1 + OFF_BHI, bhi, k1, K, tid);
            load_tile_half(st1 + OFF_BLO, blo, k1, K, tid);
            CP_COMMIT();
            CP_WAIT(1);
        } else {
            CP_WAIT(0);
        }
        __syncthreads();

        const uint32_t st = sbase + (uint32_t)s * STAGE_BYTES;
#pragma unroll
        for (int kk = 0; kk < BK; kk += 16) {
            // B fragments for this k-step: 16 regs
            uint32_t bh[4][2], bl[4][2];
#pragma unroll
            for (int nt = 0; nt < 4; nt++) {
                uint32_t ro = (uint32_t)((wn + nt * 8 + lr) * LDT + kk + bK) * 2;
                ldsm_x2(bh[nt], st + OFF_BHI + ro);
                ldsm_x2(bl[nt], st + OFF_BLO + ro);
            }
            // mt-major: only one row's A fragments live at a time (8 regs)
#pragma unroll
            for (int mt = 0; mt < 4; mt++) {
                uint32_t ah[4], al[4];
                uint32_t ro = (uint32_t)((wm + mt * 16 + aRow) * LDT + kk + aK) * 2;
                ldsm_x4(ah, st + OFF_AHI + ro);
                ldsm_x4(al, st + OFF_ALO + ro);
#pragma unroll
                for (int nt = 0; nt < 4; nt++) {
                    mma16816(acc[mt][nt], ah, bh[nt]);   // hi*hi
                    mma16816(acc[mt][nt], ah, bl[nt]);   // hi*lo
                    mma16816(acc[mt][nt], al, bh[nt]);   // lo*hi
                }
            }
        }
        __syncthreads();
    }

    // epilogue
    const int er = lid >> 2, ec = (lid & 3) * 2;
#pragma unroll
    for (int mt = 0; mt < 4; mt++)
#pragma unroll
        for (int nt = 0; nt < 4; nt++) {
            int row = wm + mt * 16 + er;
            int col = wn + nt * 8 + ec;
            *(float2*)&c[(size_t)row * Ntot + col] =
                make_float2(acc[mt][nt][0], acc[mt][nt][1]);
            *(float2*)&c[(size_t)(row + 8) * Ntot + col] =
                make_float2(acc[mt][nt][2], acc[mt][nt][3]);
        }
}

// ---------------- helper kernels --------------------------------------------
__global__ void fold_wo_kernel(const float* __restrict__ Wo) {
    int idx = blockIdx.x * blockDim.x + threadIdx.x;
    if (idx >= NG * KVDIM * NEMB) return;
    int o = idx % NEMB;
    int cc = (idx / NEMB) % KVDIM;
    int g = idx / (KVDIM * NEMB);
    int kv = cc / NHD, d = cc % NHD;
    const float* wo = Wo + (size_t)g * NEMB * NEMB;
    float s = 0.f;
#pragma unroll
    for (int r = 0; r < NRAT; r++)
        s += wo[(size_t)((kv * NRAT + r) * NHD + d) * NEMB + o];
    g_weff[idx] = 64.0f * s;
}

__global__ void split_kernel(const float* __restrict__ in,
                             __nv_bfloat16* __restrict__ hi,
                             __nv_bfloat16* __restrict__ lo, size_t n4) {
    size_t i = (size_t)blockIdx.x * blockDim.x + threadIdx.x;
    if (i >= n4) return;
    float4 v = ((const float4*)in)[i];
    __nv_bfloat16 h0 = __float2bfloat16(v.x), h1 = __float2bfloat16(v.y);
    __nv_bfloat16 h2 = __float2bfloat16(v.z), h3 = __float2bfloat16(v.w);
    __nv_bfloat16 l0 = __float2bfloat16(v.x - __bfloat162float(h0));
    __nv_bfloat16 l1 = __float2bfloat16(v.y - __bfloat162float(h1));
    __nv_bfloat16 l2 = __float2bfloat16(v.z - __bfloat162float(h2));
    __nv_bfloat16 l3 = __float2bfloat16(v.w - __bfloat162float(h3));
    ushort4 hv, lv;
    hv.x = *(unsigned short*)&h0; hv.y = *(unsigned short*)&h1;
    hv.z = *(unsigned short*)&h2; hv.w = *(unsigned short*)&h3;
    lv.x = *(unsigned short*)&l0; lv.y = *(unsigned short*)&l1;
    lv.z = *(unsigned short*)&l2; lv.w = *(unsigned short*)&l3;
    ((ushort4*)hi)[i] = hv;
    ((ushort4*)lo)[i] = lv;
}

__global__ void transpose_split_kernel(const float* __restrict__ in,
                                       __nv_bfloat16* __restrict__ hi,
                                       __nv_bfloat16* __restrict__ lo,
                                       int R, int Cc) {
    __shared__ float t[32][33];
    const int g = blockIdx.z;
    const int cB = blockIdx.x * 32, rB = blockIdx.y * 32;
    const int tx = threadIdx.x, ty = threadIdx.y;
    const float* I = in + (size_t)g * R * Cc;
#pragma unroll
    for (int j = 0; j < 4; j++)
        t[ty + j * 8][tx] = I[(size_t)(rB + ty + j * 8) * Cc + cB + tx];
    __syncthreads();
    __nv_bfloat16* H = hi + (size_t)g * R * Cc;
    __nv_bfloat16* L = lo + (size_t)g * R * Cc;
#pragma unroll
    for (int j = 0; j < 4; j++) {
        float x = t[tx][ty + j * 8];
        __nv_bfloat16 h = __float2bfloat16(x);
        __nv_bfloat16 l = __float2bfloat16(x - __bfloat162float(h));
        size_t o = (size_t)(cB + ty + j * 8) * R + rB + tx;
        H[o] = h; L[o] = l;
    }
}

// ---------------- launch -----------------------------------------------------
extern "C" void kernel_launch(void* const* d_in, const int* in_sizes, int n_in,
                              void* d_out, int out_size) {
    const float* tensor = (const float*)d_in[0];
    const float* Wv = (const float*)d_in[3];
    const float* Wo = (const float*)d_in[4];
    float* out = (float*)d_out;

    cudaFuncSetAttribute(gemm_hmma_kernel,
                         cudaFuncAttributeMaxDynamicSharedMemorySize, SMEM_TOTAL);

    __nv_bfloat16 *wvhi, *wvlo, *bthi, *btlo, *bhi, *blo, *xhi, *xlo;
    float *weff, *wcomb;
    cudaGetSymbolAddress((void**)&weff,  g_weff);
    cudaGetSymbolAddress((void**)&wcomb, g_wcomb);
    cudaGetSymbolAddress((void**)&wvhi,  g_wvhi);
    cudaGetSymbolAddress((void**)&wvlo,  g_wvlo);
    cudaGetSymbolAddress((void**)&bthi,  g_bthi);
    cudaGetSymbolAddress((void**)&btlo,  g_btlo);
    cudaGetSymbolAddress((void**)&bhi,   g_bhi);
    cudaGetSymbolAddress((void**)&blo,   g_blo);
    cudaGetSymbolAddress((void**)&xhi,   g_xhi);
    cudaGetSymbolAddress((void**)&xlo,   g_xlo);

    // 1. fold Wo -> Weff fp32 [g][256][1024]
    fold_wo_kernel<<<(NG * KVDIM * NEMB + 255) / 256, 256>>>(Wo);
    // 2. split Wv ([1024][256] K-major)
    {
        size_t n4 = (size_t)NG * NEMB * KVDIM / 4;
        split_kernel<<<(unsigned)((n4 + 255) / 256), 256>>>(Wv, wvhi, wvlo, n4);
    }
    // 3. transpose+split Weff [256][1024] -> [1024][256]
    {
        dim3 grid(NEMB / 32, KVDIM / 32, NG);
        transpose_split_kernel<<<grid, dim3(32, 8)>>>(weff, bthi, btlo, KVDIM, NEMB);
    }
    // 4. GEMM2: Wcomb = Wv @ Weff   (M=N=1024, K=256)
    {
        dim3 grid(NEMB / BN, NEMB / BM, NG);
        gemm_hmma_kernel<<<grid, 256, SMEM_TOTAL>>>(wvhi, wvlo, bthi, btlo,
                                                    wcomb, KVDIM, NEMB, NEMB);
    }
    // 5. transpose+split Wcomb [1024][1024] -> B3 [1024][1024]
    {
        dim3 grid(NEMB / 32, NEMB / 32, NG);
        transpose_split_kernel<<<grid, dim3(32, 8)>>>(wcomb, bhi, blo, NEMB, NEMB);
    }
    // 6. split X
    {
        size_t n4 = (size_t)NG * MROWS * NEMB / 4;
        split_kernel<<<(unsigned)((n4 + 255) / 256), 256>>>(tensor, xhi, xlo, n4);
    }
    // 7. GEMM3: out = X @ Wcomb   (M=4096/genome, N=1024, K=1024)
    {
        dim3 grid(NEMB / BN, MROWS / BM, NG);
        gemm_hmma_kernel<<<grid, 256, SMEM_TOTAL>>>(xhi, xlo, bhi, blo,
                                                    out, NEMB, MROWS, NEMB);
    }
}

// round 6
// speedup vs baseline: 3.1485x; 1.2647x over previous
#include <cuda_runtime.h>
#include <cuda_bf16.h>
#include <cuda_fp16.h>
#include <cstdint>

// ============================================================================
// GroupedMultiQueryAttention — algebraic reduction + HMMA split GEMMs.
//
// attention = 64 * v  (softmax rows sum to 1; q,k summed out), so
//   out[g] = X[g] @ (Wv[g] @ Weff[g]),  Weff folds 64x + head broadcast of Wo.
// GEMM2 (small, precision anchor): bf16 hi/lo 3-term  -> err ~1e-5
// GEMM3 (large): A = X in SINGLE fp16 (err 2^-12), B = Wcomb fp16 hi/lo 2-term
//   -> 2 MMA terms instead of 3, global rel err ~1.4e-4 (<< 1e-3 gate).
// ============================================================================

#define NG    8
#define NEMB  1024
#define KVDIM 256
#define MROWS 4096
#define NRAT  4
#define NHD   64

// ---------------- static device scratch -------------------------------------
__device__ float g_weff [NG * KVDIM * NEMB];
__device__ float g_wcomb[NG * NEMB * NEMB];
__device__ __nv_bfloat16 g_wvhi[NG * NEMB * KVDIM];
__device__ __nv_bfloat16 g_wvlo[NG * NEMB * KVDIM];
__device__ __nv_bfloat16 g_bthi[NG * NEMB * KVDIM];
__device__ __nv_bfloat16 g_btlo[NG * NEMB * KVDIM];
__device__ __half g_bhi [NG * NEMB * NEMB];          // WcombT fp16 hi
__device__ __half g_blo [NG * NEMB * NEMB];          // WcombT fp16 lo
__device__ __half g_xh  [(size_t)NG * MROWS * NEMB]; // X fp16 (single)

// ---------------- PTX helpers ------------------------------------------------
__device__ __forceinline__ uint32_t smem_u32(const void* p) {
    uint32_t a;
    asm("{ .reg .u64 t; cvta.to.shared.u64 t, %1; cvt.u32.u64 %0, t; }" : "=r"(a) : "l"(p));
    return a;
}
__device__ __forceinline__ void cp16(uint32_t dst, const void* src) {
    asm volatile("cp.async.cg.shared.global [%0], [%1], 16;" :: "r"(dst), "l"(src));
}
#define CP_COMMIT() asm volatile("cp.async.commit_group;" ::: "memory")
#define CP_WAIT(n)  asm volatile("cp.async.wait_group %0;" :: "n"(n) : "memory")

__device__ __forceinline__ void ldsm_x4(uint32_t* r, uint32_t addr) {
    asm volatile("ldmatrix.sync.aligned.m8n8.x4.shared.b16 {%0,%1,%2,%3}, [%4];"
                 : "=r"(r[0]), "=r"(r[1]), "=r"(r[2]), "=r"(r[3]) : "r"(addr));
}
__device__ __forceinline__ void ldsm_x2(uint32_t* r, uint32_t addr) {
    asm volatile("ldmatrix.sync.aligned.m8n8.x2.shared.b16 {%0,%1}, [%2];"
                 : "=r"(r[0]), "=r"(r[1]) : "r"(addr));
}
__device__ __forceinline__ void mma_bf16(float* d, const uint32_t* a, const uint32_t* b) {
    asm volatile("mma.sync.aligned.m16n8k16.row.col.f32.bf16.bf16.f32 "
                 "{%0,%1,%2,%3}, {%4,%5,%6,%7}, {%8,%9}, {%0,%1,%2,%3};"
                 : "+f"(d[0]), "+f"(d[1]), "+f"(d[2]), "+f"(d[3])
                 : "r"(a[0]), "r"(a[1]), "r"(a[2]), "r"(a[3]), "r"(b[0]), "r"(b[1]));
}
__device__ __forceinline__ void mma_fp16(float* d, const uint32_t* a, const uint32_t* b) {
    asm volatile("mma.sync.aligned.m16n8k16.row.col.f32.f16.f16.f32 "
                 "{%0,%1,%2,%3}, {%4,%5,%6,%7}, {%8,%9}, {%0,%1,%2,%3};"
                 : "+f"(d[0]), "+f"(d[1]), "+f"(d[2]), "+f"(d[3])
                 : "r"(a[0]), "r"(a[1]), "r"(a[2]), "r"(a[3]), "r"(b[0]), "r"(b[1]));
}

// ---------------- shared tiling constants ------------------------------------
#define BM 128
#define BN 128
#define BK 32
#define LDT 40                               // padded smem row stride (elems)
#define TILE_B (128 * LDT * 2)               // one 128xBK b16 tile: 10240 B

// fill one 128 x BK b16 tile: 256 threads x 2 cp16
template <typename T>
__device__ __forceinline__ void load_tile(uint32_t dst, const T* __restrict__ src,
                                          int k0, int K, int tid) {
#pragma unroll
    for (int i = 0; i < 2; i++) {
        int op = tid + i * 256;
        int row = op >> 2, c = op & 3;
        uint32_t off = (uint32_t)(row * LDT + c * 8) * 2;
        cp16(dst + off, src + (size_t)row * K + k0 + c * 8);
    }
}

// ============================================================================
// GEMM A: bf16 3-term split (used for GEMM2) — 2-stage pipeline
// ============================================================================
#define OFF_AHI 0
#define OFF_ALO (TILE_B)
#define OFF_BHI (TILE_B * 2)
#define OFF_BLO (TILE_B * 3)
#define STAGE_A (TILE_B * 4)                 // 40960
#define SMEM_A_TOT (2 * STAGE_A)             // 81920

__global__ void __launch_bounds__(256, 2)
gemm_bf16x3_kernel(const __nv_bfloat16* __restrict__ Ahi, const __nv_bfloat16* __restrict__ Alo,
                   const __nv_bfloat16* __restrict__ Bhi, const __nv_bfloat16* __restrict__ Blo,
                   float* __restrict__ C, int K, int Mg, int Ntot) {
    extern __shared__ char smem[];
    const uint32_t sbase = smem_u32(smem);
    const int tid = threadIdx.x, wid = tid >> 5, lid = tid & 31;
    const int g = blockIdx.z;
    const int mBase = blockIdx.y * BM, nBase = blockIdx.x * BN;

    const __nv_bfloat16* ahi = Ahi + (size_t)g * Mg * K + (size_t)mBase * K;
    const __nv_bfloat16* alo = Alo + (size_t)g * Mg * K + (size_t)mBase * K;
    const __nv_bfloat16* bhi = Bhi + (size_t)g * Ntot * K + (size_t)nBase * K;
    const __nv_bfloat16* blo = Blo + (size_t)g * Ntot * K + (size_t)nBase * K;
    float* c = C + (size_t)g * Mg * Ntot + (size_t)mBase * Ntot + nBase;

    const int wm = (wid >> 2) * 64, wn = (wid & 3) * 32;
    const int lr = lid & 7, ls = lid >> 3;
    const uint32_t aRow = (uint32_t)((ls & 1) * 8 + lr);
    const uint32_t aK   = (uint32_t)((ls >> 1) * 8);
    const uint32_t bK   = (uint32_t)((ls & 1) * 8);

    float acc[4][4][4];
#pragma unroll
    for (int mt = 0; mt < 4; mt++)
#pragma unroll
        for (int nt = 0; nt < 4; nt++)
#pragma unroll
            for (int q = 0; q < 4; q++) acc[mt][nt][q] = 0.f;

    const int nk = K / BK;
    load_tile(sbase + OFF_AHI, ahi, 0, K, tid);
    load_tile(sbase + OFF_ALO, alo, 0, K, tid);
    load_tile(sbase + OFF_BHI, bhi, 0, K, tid);
    load_tile(sbase + OFF_BLO, blo, 0, K, tid);
    CP_COMMIT();

    for (int it = 0; it < nk; ++it) {
        const int s = it & 1;
        if (it + 1 < nk) {
            const uint32_t st1 = sbase + (uint32_t)(s ^ 1) * STAGE_A;
            const int k1 = (it + 1) * BK;
            load_tile(st1 + OFF_AHI, ahi, k1, K, tid);
            load_tile(st1 + OFF_ALO, alo, k1, K, tid);
            load_tile(st1 + OFF_BHI, bhi, k1, K, tid);
            load_tile(st1 + OFF_BLO, blo, k1, K, tid);
            CP_COMMIT();
            CP_WAIT(1);
        } else {
            CP_WAIT(0);
        }
        __syncthreads();

        const uint32_t st = sbase + (uint32_t)s * STAGE_A;
#pragma unroll
        for (int kk = 0; kk < BK; kk += 16) {
            uint32_t bh[4][2], bl[4][2];
#pragma unroll
            for (int nt = 0; nt < 4; nt++) {
                uint32_t ro = (uint32_t)((wn + nt * 8 + lr) * LDT + kk + bK) * 2;
                ldsm_x2(bh[nt], st + OFF_BHI + ro);
                ldsm_x2(bl[nt], st + OFF_BLO + ro);
            }
#pragma unroll
            for (int mt = 0; mt < 4; mt++) {
                uint32_t ah[4], al[4];
                uint32_t ro = (uint32_t)((wm + mt * 16 + aRow) * LDT + kk + aK) * 2;
                ldsm_x4(ah, st + OFF_AHI + ro);
                ldsm_x4(al, st + OFF_ALO + ro);
#pragma unroll
                for (int nt = 0; nt < 4; nt++) {
                    mma_bf16(acc[mt][nt], ah, bh[nt]);
                    mma_bf16(acc[mt][nt], ah, bl[nt]);
                    mma_bf16(acc[mt][nt], al, bh[nt]);
                }
            }
        }
        __syncthreads();
    }

    const int er = lid >> 2, ec = (lid & 3) * 2;
#pragma unroll
    for (int mt = 0; mt < 4; mt++)
#pragma unroll
        for (int nt = 0; nt < 4; nt++) {
            int row = wm + mt * 16 + er, col = wn + nt * 8 + ec;
            *(float2*)&c[(size_t)row * Ntot + col] =
                make_float2(acc[mt][nt][0], acc[mt][nt][1]);
            *(float2*)&c[(size_t)(row + 8) * Ntot + col] =
                make_float2(acc[mt][nt][2], acc[mt][nt][3]);
        }
}

// ============================================================================
// GEMM B: fp16, A single / B hi-lo 2-term (GEMM3) — 3-stage pipeline
// ============================================================================
#define OFF3_A   0
#define OFF3_BHI (TILE_B)
#define OFF3_BLO (TILE_B * 2)
#define STAGE3   (TILE_B * 3)                // 30720
#define NST3     3
#define SMEM3_TOT (NST3 * STAGE3)            // 92160

__global__ void __launch_bounds__(256, 2)
gemm_fp16x2_kernel(const __half* __restrict__ A,
                   const __half* __restrict__ Bhi, const __half* __restrict__ Blo,
                   float* __restrict__ C, int K, int Mg, int Ntot) {
    extern __shared__ char smem[];
    const uint32_t sbase = smem_u32(smem);
    const int tid = threadIdx.x, wid = tid >> 5, lid = tid & 31;
    const int g = blockIdx.z;
    const int mBase = blockIdx.y * BM, nBase = blockIdx.x * BN;

    const __half* a0  = A   + (size_t)g * Mg * K + (size_t)mBase * K;
    const __half* bhi = Bhi + (size_t)g * Ntot * K + (size_t)nBase * K;
    const __half* blo = Blo + (size_t)g * Ntot * K + (size_t)nBase * K;
    float* c = C + (size_t)g * Mg * Ntot + (size_t)mBase * Ntot + nBase;

    const int wm = (wid >> 2) * 64, wn = (wid & 3) * 32;
    const int lr = lid & 7, ls = lid >> 3;
    const uint32_t aRow = (uint32_t)((ls & 1) * 8 + lr);
    const uint32_t aK   = (uint32_t)((ls >> 1) * 8);
    const uint32_t bK   = (uint32_t)((ls & 1) * 8);

    float acc[4][4][4];
#pragma unroll
    for (int mt = 0; mt < 4; mt++)
#pragma unroll
        for (int nt = 0; nt < 4; nt++)
#pragma unroll
            for (int q = 0; q < 4; q++) acc[mt][nt][q] = 0.f;

    const int nk = K / BK;        // >= 3 here (K=1024)
    // prologue: stages 0 and 1
#pragma unroll
    for (int p = 0; p < 2; p++) {
        const uint32_t st = sbase + (uint32_t)p * STAGE3;
        load_tile(st + OFF3_A,   a0,  p * BK, K, tid);
        load_tile(st + OFF3_BHI, bhi, p * BK, K, tid);
        load_tile(st + OFF3_BLO, blo, p * BK, K, tid);
        CP_COMMIT();
    }

    int sIdx = 0;
    for (int it = 0; it < nk; ++it) {
        if (it + 2 < nk) {
            int s2 = sIdx + 2; if (s2 >= NST3) s2 -= NST3;
            const uint32_t st2 = sbase + (uint32_t)s2 * STAGE3;
            const int k2 = (it + 2) * BK;
            load_tile(st2 + OFF3_A,   a0,  k2, K, tid);
            load_tile(st2 + OFF3_BHI, bhi, k2, K, tid);
            load_tile(st2 + OFF3_BLO, blo, k2, K, tid);
        }
        CP_COMMIT();
        CP_WAIT(2);
        __syncthreads();

        const uint32_t st = sbase + (uint32_t)sIdx * STAGE3;
#pragma unroll
        for (int kk = 0; kk < BK; kk += 16) {
            uint32_t bh[4][2], bl[4][2];
#pragma unroll
            for (int nt = 0; nt < 4; nt++) {
                uint32_t ro = (uint32_t)((wn + nt * 8 + lr) * LDT + kk + bK) * 2;
                ldsm_x2(bh[nt], st + OFF3_BHI + ro);
                ldsm_x2(bl[nt], st + OFF3_BLO + ro);
            }
#pragma unroll
            for (int mt = 0; mt < 4; mt++) {
                uint32_t a[4];
                uint32_t ro = (uint32_t)((wm + mt * 16 + aRow) * LDT + kk + aK) * 2;
                ldsm_x4(a, st + OFF3_A + ro);
#pragma unroll
                for (int nt = 0; nt < 4; nt++) {
                    mma_fp16(acc[mt][nt], a, bh[nt]);
                    mma_fp16(acc[mt][nt], a, bl[nt]);
                }
            }
        }
        __syncthreads();
        if (++sIdx == NST3) sIdx = 0;
    }

    const int er = lid >> 2, ec = (lid & 3) * 2;
#pragma unroll
    for (int mt = 0; mt < 4; mt++)
#pragma unroll
        for (int nt = 0; nt < 4; nt++) {
            int row = wm + mt * 16 + er, col = wn + nt * 8 + ec;
            *(float2*)&c[(size_t)row * Ntot + col] =
                make_float2(acc[mt][nt][0], acc[mt][nt][1]);
            *(float2*)&c[(size_t)(row + 8) * Ntot + col] =
                make_float2(acc[mt][nt][2], acc[mt][nt][3]);
        }
}

// ---------------- helper kernels --------------------------------------------
__global__ void fold_wo_kernel(const float* __restrict__ Wo) {
    int idx = blockIdx.x * blockDim.x + threadIdx.x;
    if (idx >= NG * KVDIM * NEMB) return;
    int o = idx % NEMB;
    int cc = (idx / NEMB) % KVDIM;
    int g = idx / (KVDIM * NEMB);
    int kv = cc / NHD, d = cc % NHD;
    const float* wo = Wo + (size_t)g * NEMB * NEMB;
    float s = 0.f;
#pragma unroll
    for (int r = 0; r < NRAT; r++)
        s += wo[(size_t)((kv * NRAT + r) * NHD + d) * NEMB + o];
    g_weff[idx] = 64.0f * s;
}

// fp32 -> bf16 hi/lo split
__global__ void split_bf16_kernel(const float* __restrict__ in,
                                  __nv_bfloat16* __restrict__ hi,
                                  __nv_bfloat16* __restrict__ lo, size_t n4) {
    size_t i = (size_t)blockIdx.x * blockDim.x + threadIdx.x;
    if (i >= n4) return;
    float4 v = ((const float4*)in)[i];
    __nv_bfloat16 h0 = __float2bfloat16(v.x), h1 = __float2bfloat16(v.y);
    __nv_bfloat16 h2 = __float2bfloat16(v.z), h3 = __float2bfloat16(v.w);
    __nv_bfloat16 l0 = __float2bfloat16(v.x - __bfloat162float(h0));
    __nv_bfloat16 l1 = __float2bfloat16(v.y - __bfloat162float(h1));
    __nv_bfloat16 l2 = __float2bfloat16(v.z - __bfloat162float(h2));
    __nv_bfloat16 l3 = __float2bfloat16(v.w - __bfloat162float(h3));
    ushort4 hv, lv;
    hv.x = *(unsigned short*)&h0; hv.y = *(unsigned short*)&h1;
    hv.z = *(unsigned short*)&h2; hv.w = *(unsigned short*)&h3;
    lv.x = *(unsigned short*)&l0; lv.y = *(unsigned short*)&l1;
    lv.z = *(unsigned short*)&l2; lv.w = *(unsigned short*)&l3;
    ((ushort4*)hi)[i] = hv;
    ((ushort4*)lo)[i] = lv;
}

// fp32 -> fp16 single convert (for X)
__global__ void convert_half_kernel(const float* __restrict__ in,
                                    __half* __restrict__ out, size_t n4) {
    size_t i = (size_t)blockIdx.x * blockDim.x + threadIdx.x;
    if (i >= n4) return;
    float4 v = ((const float4*)in)[i];
    __half2 h01 = __floats2half2_rn(v.x, v.y);
    __half2 h23 = __floats2half2_rn(v.z, v.w);
    uint2 o;
    o.x = *(uint32_t*)&h01; o.y = *(uint32_t*)&h23;
    ((uint2*)out)[i] = o;
}

// per-genome transpose + split (bf16 variant, for Weff)
__global__ void transpose_split_bf16_kernel(const float* __restrict__ in,
                                            __nv_bfloat16* __restrict__ hi,
                                            __nv_bfloat16* __restrict__ lo,
                                            int R, int Cc) {
    __shared__ float t[32][33];
    const int g = blockIdx.z;
    const int cB = blockIdx.x * 32, rB = blockIdx.y * 32;
    const int tx = threadIdx.x, ty = threadIdx.y;
    const float* I = in + (size_t)g * R * Cc;
#pragma unroll
    for (int j = 0; j < 4; j++)
        t[ty + j * 8][tx] = I[(size_t)(rB + ty + j * 8) * Cc + cB + tx];
    __syncthreads();
    __nv_bfloat16* H = hi + (size_t)g * R * Cc;
    __nv_bfloat16* L = lo + (size_t)g * R * Cc;
#pragma unroll
    for (int j = 0; j < 4; j++) {
        float x = t[tx][ty + j * 8];
        __nv_bfloat16 h = __float2bfloat16(x);
        __nv_bfloat16 l = __float2bfloat16(x - __bfloat162float(h));
        size_t o = (size_t)(cB + ty + j * 8) * R + rB + tx;
        H[o] = h; L[o] = l;
    }
}

// per-genome transpose + split (fp16 variant, for Wcomb)
__global__ void transpose_split_fp16_kernel(const float* __restrict__ in,
                                            __half* __restrict__ hi,
                                            __half* __restrict__ lo,
                                            int R, int Cc) {
    __shared__ float t[32][33];
    const int g = blockIdx.z;
    const int cB = blockIdx.x * 32, rB = blockIdx.y * 32;
    const int tx = threadIdx.x, ty = threadIdx.y;
    const float* I = in + (size_t)g * R * Cc;
#pragma unroll
    for (int j = 0; j < 4; j++)
        t[ty + j * 8][tx] = I[(size_t)(rB + ty + j * 8) * Cc + cB + tx];
    __syncthreads();
    __half* H = hi + (size_t)g * R * Cc;
    __half* L = lo + (size_t)g * R * Cc;
#pragma unroll
    for (int j = 0; j < 4; j++) {
        float x = t[tx][ty + j * 8];
        __half h = __float2half_rn(x);
        __half l = __float2half_rn(x - __half2float(h));
        size_t o = (size_t)(cB + ty + j * 8) * R + rB + tx;
        H[o] = h; L[o] = l;
    }
}

// ---------------- launch -----------------------------------------------------
extern "C" void kernel_launch(void* const* d_in, const int* in_sizes, int n_in,
                              void* d_out, int out_size) {
    const float* tensor = (const float*)d_in[0];
    const float* Wv = (const float*)d_in[3];
    const float* Wo = (const float*)d_in[4];
    float* out = (float*)d_out;

    cudaFuncSetAttribute(gemm_bf16x3_kernel,
                         cudaFuncAttributeMaxDynamicSharedMemorySize, SMEM_A_TOT);
    cudaFuncSetAttribute(gemm_fp16x2_kernel,
                         cudaFuncAttributeMaxDynamicSharedMemorySize, SMEM3_TOT);

    __nv_bfloat16 *wvhi, *wvlo, *bthi, *btlo;
    __half *bhi, *blo, *xh;
    float *weff, *wcomb;
    cudaGetSymbolAddress((void**)&weff,  g_weff);
    cudaGetSymbolAddress((void**)&wcomb, g_wcomb);
    cudaGetSymbolAddress((void**)&wvhi,  g_wvhi);
    cudaGetSymbolAddress((void**)&wvlo,  g_wvlo);
    cudaGetSymbolAddress((void**)&bthi,  g_bthi);
    cudaGetSymbolAddress((void**)&btlo,  g_btlo);
    cudaGetSymbolAddress((void**)&bhi,   g_bhi);
    cudaGetSymbolAddress((void**)&blo,   g_blo);
    cudaGetSymbolAddress((void**)&xh,    g_xh);

    // 1. fold Wo -> Weff fp32 [g][256][1024]
    fold_wo_kernel<<<(NG * KVDIM * NEMB + 255) / 256, 256>>>(Wo);
    // 2. split Wv -> bf16 hi/lo ([1024][256] K-major)
    {
        size_t n4 = (size_t)NG * NEMB * KVDIM / 4;
        split_bf16_kernel<<<(unsigned)((n4 + 255) / 256), 256>>>(Wv, wvhi, wvlo, n4);
    }
    // 3. transpose+split Weff [256][1024] -> bf16 [1024][256]
    {
        dim3 grid(NEMB / 32, KVDIM / 32, NG);
        transpose_split_bf16_kernel<<<grid, dim3(32, 8)>>>(weff, bthi, btlo, KVDIM, NEMB);
    }
    // 4. GEMM2 (bf16 3-term): Wcomb = Wv @ Weff  (M=N=1024, K=256)
    {
        dim3 grid(NEMB / BN, NEMB / BM, NG);
        gemm_bf16x3_kernel<<<grid, 256, SMEM_A_TOT>>>(wvhi, wvlo, bthi, btlo,
                                                      wcomb, KVDIM, NEMB, NEMB);
    }
    // 5. transpose+split Wcomb [1024][1024] -> fp16 hi/lo [1024][1024]
    {
        dim3 grid(NEMB / 32, NEMB / 32, NG);
        transpose_split_fp16_kernel<<<grid, dim3(32, 8)>>>(wcomb, bhi, blo, NEMB, NEMB);
    }
    // 6. convert X -> fp16 single
    {
        size_t n4 = (size_t)NG * MROWS * NEMB / 4;
        convert_half_kernel<<<(unsigned)((n4 + 255) / 256), 256>>>(tensor, xh, n4);
    }
    // 7. GEMM3 (fp16, 2-term): out = X @ Wcomb  (M=4096/genome, N=1024, K=1024)
    {
        dim3 grid(NEMB / BN, MROWS / BM, NG);
        gemm_fp16x2_kernel<<<grid, 256, SMEM3_TOT>>>(xh, bhi, blo,
                                                     out, NEMB, MROWS, NEMB);
    }
}

// round 7
// speedup vs baseline: 4.6706x; 1.4835x over previous
#include <cuda_runtime.h>
#include <cuda_bf16.h>
#include <cuda_fp16.h>
#include <cstdint>

// ============================================================================
// GroupedMultiQueryAttention — algebraic reduction + HMMA fp16 GEMMs.
//
// attention = 64 * v  (softmax rows sum to 1; q,k summed out), so
//   out[g] = X[g] @ Wcomb[g],  Wcomb = Wv @ Weff,  Weff = 64*head-folded Wo.
// Round 7:
//  - GEMM2 computes WcombT = WeffT @ WvT directly (both operands K-major
//    already) with fp16 hi/lo 3-term precision, fused fp16-single epilogue.
//    No fp32 Wcomb buffer, no transpose pass.
//  - GEMM3: fp16 single x single (1 MMA term), 4-stage cp.async pipeline.
//    Error budget (calibrated R6): X-trunc ~2e-4 (+) Wcomb-repr ~2.8e-4
//    -> ~3.5e-4 total, 2.9x under the 1e-3 gate.
// ============================================================================

#define NG    8
#define NEMB  1024
#define KVDIM 256
#define MROWS 4096
#define NRAT  4
#define NHD   64

// ---------------- static device scratch -------------------------------------
__device__ __half g_wthi[NG * NEMB * KVDIM];          // WeffT hi  [g][o=1024][c=256]
__device__ __half g_wtlo[NG * NEMB * KVDIM];          // WeffT lo
__device__ __half g_wvhi[NG * NEMB * KVDIM];          // Wv hi     [g][m=1024][c=256]
__device__ __half g_wvlo[NG * NEMB * KVDIM];          // Wv lo
__device__ __half g_bh  [NG * NEMB * NEMB];           // WcombT fp16 [g][o][m]
__device__ __half g_xh  [(size_t)NG * MROWS * NEMB];  // X fp16

// ---------------- PTX helpers ------------------------------------------------
__device__ __forceinline__ uint32_t smem_u32(const void* p) {
    uint32_t a;
    asm("{ .reg .u64 t; cvta.to.shared.u64 t, %1; cvt.u32.u64 %0, t; }" : "=r"(a) : "l"(p));
    return a;
}
__device__ __forceinline__ void cp16(uint32_t dst, const void* src) {
    asm volatile("cp.async.cg.shared.global [%0], [%1], 16;" :: "r"(dst), "l"(src));
}
#define CP_COMMIT() asm volatile("cp.async.commit_group;" ::: "memory")
#define CP_WAIT(n)  asm volatile("cp.async.wait_group %0;" :: "n"(n) : "memory")

__device__ __forceinline__ void ldsm_x4(uint32_t* r, uint32_t addr) {
    asm volatile("ldmatrix.sync.aligned.m8n8.x4.shared.b16 {%0,%1,%2,%3}, [%4];"
                 : "=r"(r[0]), "=r"(r[1]), "=r"(r[2]), "=r"(r[3]) : "r"(addr));
}
__device__ __forceinline__ void ldsm_x2(uint32_t* r, uint32_t addr) {
    asm volatile("ldmatrix.sync.aligned.m8n8.x2.shared.b16 {%0,%1}, [%2];"
                 : "=r"(r[0]), "=r"(r[1]) : "r"(addr));
}
__device__ __forceinline__ void mma_fp16(float* d, const uint32_t* a, const uint32_t* b) {
    asm volatile("mma.sync.aligned.m16n8k16.row.col.f32.f16.f16.f32 "
                 "{%0,%1,%2,%3}, {%4,%5,%6,%7}, {%8,%9}, {%0,%1,%2,%3};"
                 : "+f"(d[0]), "+f"(d[1]), "+f"(d[2]), "+f"(d[3])
                 : "r"(a[0]), "r"(a[1]), "r"(a[2]), "r"(a[3]), "r"(b[0]), "r"(b[1]));
}

// ---------------- shared tiling constants ------------------------------------
#define BM 128
#define BN 128
#define BK 32
#define LDT 40                               // padded smem row stride (elems)
#define TILE_B (128 * LDT * 2)               // one 128xBK fp16 tile: 10240 B

template <typename T>
__device__ __forceinline__ void load_tile(uint32_t dst, const T* __restrict__ src,
                                          int k0, int K, int tid) {
#pragma unroll
    for (int i = 0; i < 2; i++) {
        int op = tid + i * 256;
        int row = op >> 2, c = op & 3;
        uint32_t off = (uint32_t)(row * LDT + c * 8) * 2;
        cp16(dst + off, src + (size_t)row * K + k0 + c * 8);
    }
}

// ============================================================================
// GEMM2: WcombT[o][m] = sum_c WeffT[o][c] * Wv[m][c]
// fp16 hi/lo 3-term (precise), fused fp16-single epilogue. 2-stage pipeline.
// ============================================================================
#define OFF_AHI 0
#define OFF_ALO (TILE_B)
#define OFF_BHI (TILE_B * 2)
#define OFF_BLO (TILE_B * 3)
#define STAGE_W (TILE_B * 4)                 // 40960
#define SMEM_W_TOT (2 * STAGE_W)             // 81920

__global__ void __launch_bounds__(256, 2)
gemm_w_kernel(const __half* __restrict__ Ahi, const __half* __restrict__ Alo,
              const __half* __restrict__ Bhi, const __half* __restrict__ Blo,
              __half* __restrict__ C, int K, int Mg, int Ntot) {
    extern __shared__ char smem[];
    const uint32_t sbase = smem_u32(smem);
    const int tid = threadIdx.x, wid = tid >> 5, lid = tid & 31;
    const int g = blockIdx.z;
    const int mBase = blockIdx.y * BM, nBase = blockIdx.x * BN;

    const __half* ahi = Ahi + (size_t)g * Mg * K + (size_t)mBase * K;
    const __half* alo = Alo + (size_t)g * Mg * K + (size_t)mBase * K;
    const __half* bhi = Bhi + (size_t)g * Ntot * K + (size_t)nBase * K;
    const __half* blo = Blo + (size_t)g * Ntot * K + (size_t)nBase * K;
    __half* c = C + (size_t)g * Mg * Ntot + (size_t)mBase * Ntot + nBase;

    const int wm = (wid >> 2) * 64, wn = (wid & 3) * 32;
    const int lr = lid & 7, ls = lid >> 3;
    const uint32_t aRow = (uint32_t)((ls & 1) * 8 + lr);
    const uint32_t aK   = (uint32_t)((ls >> 1) * 8);
    const uint32_t bK   = (uint32_t)((ls & 1) * 8);

    float acc[4][4][4];
#pragma unroll
    for (int mt = 0; mt < 4; mt++)
#pragma unroll
        for (int nt = 0; nt < 4; nt++)
#pragma unroll
            for (int q = 0; q < 4; q++) acc[mt][nt][q] = 0.f;

    const int nk = K / BK;
    load_tile(sbase + OFF_AHI, ahi, 0, K, tid);
    load_tile(sbase + OFF_ALO, alo, 0, K, tid);
    load_tile(sbase + OFF_BHI, bhi, 0, K, tid);
    load_tile(sbase + OFF_BLO, blo, 0, K, tid);
    CP_COMMIT();

    for (int it = 0; it < nk; ++it) {
        const int s = it & 1;
        if (it + 1 < nk) {
            const uint32_t st1 = sbase + (uint32_t)(s ^ 1) * STAGE_W;
            const int k1 = (it + 1) * BK;
            load_tile(st1 + OFF_AHI, ahi, k1, K, tid);
            load_tile(st1 + OFF_ALO, alo, k1, K, tid);
            load_tile(st1 + OFF_BHI, bhi, k1, K, tid);
            load_tile(st1 + OFF_BLO, blo, k1, K, tid);
            CP_COMMIT();
            CP_WAIT(1);
        } else {
            CP_WAIT(0);
        }
        __syncthreads();

        const uint32_t st = sbase + (uint32_t)s * STAGE_W;
#pragma unroll
        for (int kk = 0; kk < BK; kk += 16) {
            uint32_t bh[4][2], bl[4][2];
#pragma unroll
            for (int nt = 0; nt < 4; nt++) {
                uint32_t ro = (uint32_t)((wn + nt * 8 + lr) * LDT + kk + bK) * 2;
                ldsm_x2(bh[nt], st + OFF_BHI + ro);
                ldsm_x2(bl[nt], st + OFF_BLO + ro);
            }
#pragma unroll
            for (int mt = 0; mt < 4; mt++) {
                uint32_t ah[4], al[4];
                uint32_t ro = (uint32_t)((wm + mt * 16 + aRow) * LDT + kk + aK) * 2;
                ldsm_x4(ah, st + OFF_AHI + ro);
                ldsm_x4(al, st + OFF_ALO + ro);
#pragma unroll
                for (int nt = 0; nt < 4; nt++) {
                    mma_fp16(acc[mt][nt], ah, bh[nt]);
                    mma_fp16(acc[mt][nt], ah, bl[nt]);
                    mma_fp16(acc[mt][nt], al, bh[nt]);
                }
            }
        }
        __syncthreads();
    }

    // fused epilogue: fp32 acc -> fp16 single WcombT
    const int er = lid >> 2, ec = (lid & 3) * 2;
#pragma unroll
    for (int mt = 0; mt < 4; mt++)
#pragma unroll
        for (int nt = 0; nt < 4; nt++) {
            int row = wm + mt * 16 + er, col = wn + nt * 8 + ec;
            __half2 v01 = __floats2half2_rn(acc[mt][nt][0], acc[mt][nt][1]);
            __half2 v23 = __floats2half2_rn(acc[mt][nt][2], acc[mt][nt][3]);
            *(uint32_t*)&c[(size_t)row * Ntot + col] = *(uint32_t*)&v01;
            *(uint32_t*)&c[(size_t)(row + 8) * Ntot + col] = *(uint32_t*)&v23;
        }
}

// ============================================================================
// GEMM3: out = X @ Wcomb  — fp16 single x single, 4-stage pipeline
// ============================================================================
#define OFF3_A 0
#define OFF3_B (TILE_B)
#define STAGE3 (TILE_B * 2)                  // 20480
#define NST3   4
#define SMEM3_TOT (NST3 * STAGE3)            // 81920

__global__ void __launch_bounds__(256, 2)
gemm_main_kernel(const __half* __restrict__ A, const __half* __restrict__ B,
                 float* __restrict__ C, int K, int Mg, int Ntot) {
    extern __shared__ char smem[];
    const uint32_t sbase = smem_u32(smem);
    const int tid = threadIdx.x, wid = tid >> 5, lid = tid & 31;
    const int g = blockIdx.z;
    const int mBase = blockIdx.y * BM, nBase = blockIdx.x * BN;

    const __half* a0 = A + (size_t)g * Mg * K + (size_t)mBase * K;
    const __half* b0 = B + (size_t)g * Ntot * K + (size_t)nBase * K;
    float* c = C + (size_t)g * Mg * Ntot + (size_t)mBase * Ntot + nBase;

    const int wm = (wid >> 2) * 64, wn = (wid & 3) * 32;
    const int lr = lid & 7, ls = lid >> 3;
    const uint32_t aRow = (uint32_t)((ls & 1) * 8 + lr);
    const uint32_t aK   = (uint32_t)((ls >> 1) * 8);
    const uint32_t bK   = (uint32_t)((ls & 1) * 8);

    float acc[4][4][4];
#pragma unroll
    for (int mt = 0; mt < 4; mt++)
#pragma unroll
        for (int nt = 0; nt < 4; nt++)
#pragma unroll
            for (int q = 0; q < 4; q++) acc[mt][nt][q] = 0.f;

    const int nk = K / BK;                   // 32
    // prologue: fill stages 0..2
#pragma unroll
    for (int p = 0; p < NST3 - 1; p++) {
        const uint32_t st = sbase + (uint32_t)p * STAGE3;
        load_tile(st + OFF3_A, a0, p * BK, K, tid);
        load_tile(st + OFF3_B, b0, p * BK, K, tid);
        CP_COMMIT();
    }

    int sIdx = 0;
    for (int it = 0; it < nk; ++it) {
        if (it + NST3 - 1 < nk) {
            int s3 = sIdx + NST3 - 1; if (s3 >= NST3) s3 -= NST3;
            const uint32_t st3 = sbase + (uint32_t)s3 * STAGE3;
            const int k3 = (it + NST3 - 1) * BK;
            load_tile(st3 + OFF3_A, a0, k3, K, tid);
            load_tile(st3 + OFF3_B, b0, k3, K, tid);
        }
        CP_COMMIT();
        CP_WAIT(NST3 - 1);
        __syncthreads();

        const uint32_t st = sbase + (uint32_t)sIdx * STAGE3;
#pragma unroll
        for (int kk = 0; kk < BK; kk += 16) {
            uint32_t bf[4][2];
#pragma unroll
            for (int nt = 0; nt < 4; nt++) {
                uint32_t ro = (uint32_t)((wn + nt * 8 + lr) * LDT + kk + bK) * 2;
                ldsm_x2(bf[nt], st + OFF3_B + ro);
            }
#pragma unroll
            for (int mt = 0; mt < 4; mt++) {
                uint32_t a[4];
                uint32_t ro = (uint32_t)((wm + mt * 16 + aRow) * LDT + kk + aK) * 2;
                ldsm_x4(a, st + OFF3_A + ro);
#pragma unroll
                for (int nt = 0; nt < 4; nt++)
                    mma_fp16(acc[mt][nt], a, bf[nt]);
            }
        }
        __syncthreads();
        if (++sIdx == NST3) sIdx = 0;
    }

    const int er = lid >> 2, ec = (lid & 3) * 2;
#pragma unroll
    for (int mt = 0; mt < 4; mt++)
#pragma unroll
        for (int nt = 0; nt < 4; nt++) {
            int row = wm + mt * 16 + er, col = wn + nt * 8 + ec;
            *(float2*)&c[(size_t)row * Ntot + col] =
                make_float2(acc[mt][nt][0], acc[mt][nt][1]);
            *(float2*)&c[(size_t)(row + 8) * Ntot + col] =
                make_float2(acc[mt][nt][2], acc[mt][nt][3]);
        }
}

// ---------------- helper kernels --------------------------------------------
// fused fold + transpose + fp16 hi/lo split:
// WeffT[g][o][c] = hi/lo( 64 * sum_r Wo[g][(kv*4+r)*64+d][o] ),  c = kv*64+d
__global__ void fold_transpose_kernel(const float* __restrict__ Wo,
                                      __half* __restrict__ hi,
                                      __half* __restrict__ lo) {
    __shared__ float t[32][33];
    const int g = blockIdx.z;
    const int oB = blockIdx.x * 32;          // o-dim tile base (0..1023)
    const int cB = blockIdx.y * 32;          // c-dim tile base (0..255)
    const int tx = threadIdx.x, ty = threadIdx.y;   // 32 x 8
    const float* wo = Wo + (size_t)g * NEMB * NEMB;
#pragma unroll
    for (int j = 0; j < 4; j++) {
        int cc = cB + ty + j * 8;
        int kv = cc >> 6, d = cc & 63;
        int o = oB + tx;
        float s = 0.f;
#pragma unroll
        for (int r = 0; r < NRAT; r++)
            s += wo[(size_t)((kv * NRAT + r) * NHD + d) * NEMB + o];
        t[ty + j * 8][tx] = 64.0f * s;
    }
    __syncthreads();
    __half* H = hi + (size_t)g * NEMB * KVDIM;
    __half* L = lo + (size_t)g * NEMB * KVDIM;
#pragma unroll
    for (int j = 0; j < 4; j++) {
        float x = t[tx][ty + j * 8];
        __half h = __float2half_rn(x);
        __half l = __float2half_rn(x - __half2float(h));
        size_t o = (size_t)(oB + ty + j * 8) * KVDIM + cB + tx;
        H[o] = h; L[o] = l;
    }
}

// fp32 -> fp16 hi/lo split (for Wv)
__global__ void split_fp16_kernel(const float* __restrict__ in,
                                  __half* __restrict__ hi,
                                  __half* __restrict__ lo, size_t n4) {
    size_t i = (size_t)blockIdx.x * blockDim.x + threadIdx.x;
    if (i >= n4) return;
    float4 v = ((const float4*)in)[i];
    __half h0 = __float2half_rn(v.x), h1 = __float2half_rn(v.y);
    __half h2 = __float2half_rn(v.z), h3 = __float2half_rn(v.w);
    __half l0 = __float2half_rn(v.x - __half2float(h0));
    __half l1 = __float2half_rn(v.y - __half2float(h1));
    __half l2 = __float2half_rn(v.z - __half2float(h2));
    __half l3 = __float2half_rn(v.w - __half2float(h3));
    ushort4 hv, lv;
    hv.x = *(unsigned short*)&h0; hv.y = *(unsigned short*)&h1;
    hv.z = *(unsigned short*)&h2; hv.w = *(unsigned short*)&h3;
    lv.x = *(unsigned short*)&l0; lv.y = *(unsigned short*)&l1;
    lv.z = *(unsigned short*)&l2; lv.w = *(unsigned short*)&l3;
    ((ushort4*)hi)[i] = hv;
    ((ushort4*)lo)[i] = lv;
}

// fp32 -> fp16 single convert (for X)
__global__ void convert_half_kernel(const float* __restrict__ in,
                                    __half* __restrict__ out, size_t n4) {
    size_t i = (size_t)blockIdx.x * blockDim.x + threadIdx.x;
    if (i >= n4) return;
    float4 v = ((const float4*)in)[i];
    __half2 h01 = __floats2half2_rn(v.x, v.y);
    __half2 h23 = __floats2half2_rn(v.z, v.w);
    uint2 o;
    o.x = *(uint32_t*)&h01; o.y = *(uint32_t*)&h23;
    ((uint2*)out)[i] = o;
}

// ---------------- launch -----------------------------------------------------
extern "C" void kernel_launch(void* const* d_in, const int* in_sizes, int n_in,
                              void* d_out, int out_size) {
    const float* tensor = (const float*)d_in[0];
    const float* Wv = (const float*)d_in[3];
    const float* Wo = (const float*)d_in[4];
    float* out = (float*)d_out;

    cudaFuncSetAttribute(gemm_w_kernel,
                         cudaFuncAttributeMaxDynamicSharedMemorySize, SMEM_W_TOT);
    cudaFuncSetAttribute(gemm_main_kernel,
                         cudaFuncAttributeMaxDynamicSharedMemorySize, SMEM3_TOT);

    __half *wthi, *wtlo, *wvhi, *wvlo, *bh, *xh;
    cudaGetSymbolAddress((void**)&wthi, g_wthi);
    cudaGetSymbolAddress((void**)&wtlo, g_wtlo);
    cudaGetSymbolAddress((void**)&wvhi, g_wvhi);
    cudaGetSymbolAddress((void**)&wvlo, g_wvlo);
    cudaGetSymbolAddress((void**)&bh,   g_bh);
    cudaGetSymbolAddress((void**)&xh,   g_xh);

    // 1. fold+transpose+split: Wo -> WeffT fp16 hi/lo [g][1024][256]
    {
        dim3 grid(NEMB / 32, KVDIM / 32, NG);
        fold_transpose_kernel<<<grid, dim3(32, 8)>>>(Wo, wthi, wtlo);
    }
    // 2. split Wv -> fp16 hi/lo [g][1024][256]
    {
        size_t n4 = (size_t)NG * NEMB * KVDIM / 4;
        split_fp16_kernel<<<(unsigned)((n4 + 255) / 256), 256>>>(Wv, wvhi, wvlo, n4);
    }
    // 3. GEMM2: WcombT = WeffT @ WvT (fp16 3-term, fp16 epilogue)
    {
        dim3 grid(NEMB / BN, NEMB / BM, NG);
        gemm_w_kernel<<<grid, 256, SMEM_W_TOT>>>(wthi, wtlo, wvhi, wvlo,
                                                 bh, KVDIM, NEMB, NEMB);
    }
    // 4. convert X -> fp16
    {
        size_t n4 = (size_t)NG * MROWS * NEMB / 4;
        convert_half_kernel<<<(unsigned)((n4 + 255) / 256), 256>>>(tensor, xh, n4);
    }
    // 5. GEMM3: out = X @ Wcomb (fp16 1-term, 4-stage)
    {
        dim3 grid(NEMB / BN, MROWS / BM, NG);
        gemm_main_kernel<<<grid, 256, SMEM3_TOT>>>(xh, bh, out, NEMB, MROWS, NEMB);
    }
}

// round 8
// speedup vs baseline: 6.0160x; 1.2880x over previous
#include <cuda_runtime.h>
#include <cuda_fp16.h>
#include <cstdint>

// ============================================================================
// GroupedMultiQueryAttention — algebraic reduction + fp16 HMMA GEMMs.
//
// attention = 64 * v  (softmax rows sum to 1; q,k summed out), so
//   out[g] = X[g] @ Wcomb[g],  Wcomb = Wv @ Weff,  Weff = 64*head-folded Wo.
// Round 8: single generic fp16 1-term GEMM (templated output) used for both
//   GEMM2 (WcombT = WeffT @ WvT, K=256, fp16 out) and
//   GEMM3 (out = X @ Wcomb, K=1024, fp32 out).
// BK=64, 3-stage cp.async ring, B fragments via paired ldmatrix.x4.
// Error budget: X-trunc ~2e-4 (+) Wcomb ~3.4e-4 -> ~4e-4 << 1e-3 gate.
// ============================================================================

#define NG    8
#define NEMB  1024
#define KVDIM 256
#define MROWS 4096
#define NRAT  4
#define NHD   64

// ---------------- static device scratch -------------------------------------
__device__ __half g_wt  [NG * NEMB * KVDIM];          // WeffT fp16 [g][o=1024][c=256]
__device__ __half g_wvh [NG * NEMB * KVDIM];          // Wv fp16    [g][m=1024][c=256]
__device__ __half g_bh  [NG * NEMB * NEMB];           // WcombT fp16 [g][o][m]
__device__ __half g_xh  [(size_t)NG * MROWS * NEMB];  // X fp16

// ---------------- PTX helpers ------------------------------------------------
__device__ __forceinline__ uint32_t smem_u32(const void* p) {
    uint32_t a;
    asm("{ .reg .u64 t; cvta.to.shared.u64 t, %1; cvt.u32.u64 %0, t; }" : "=r"(a) : "l"(p));
    return a;
}
__device__ __forceinline__ void cp16(uint32_t dst, const void* src) {
    asm volatile("cp.async.cg.shared.global [%0], [%1], 16;" :: "r"(dst), "l"(src));
}
#define CP_COMMIT() asm volatile("cp.async.commit_group;" ::: "memory")
#define CP_WAIT(n)  asm volatile("cp.async.wait_group %0;" :: "n"(n) : "memory")

__device__ __forceinline__ void ldsm_x4(uint32_t* r, uint32_t addr) {
    asm volatile("ldmatrix.sync.aligned.m8n8.x4.shared.b16 {%0,%1,%2,%3}, [%4];"
                 : "=r"(r[0]), "=r"(r[1]), "=r"(r[2]), "=r"(r[3]) : "r"(addr));
}
__device__ __forceinline__ void mma_fp16(float* d, const uint32_t* a, const uint32_t* b) {
    asm volatile("mma.sync.aligned.m16n8k16.row.col.f32.f16.f16.f32 "
                 "{%0,%1,%2,%3}, {%4,%5,%6,%7}, {%8,%9}, {%0,%1,%2,%3};"
                 : "+f"(d[0]), "+f"(d[1]), "+f"(d[2]), "+f"(d[3])
                 : "r"(a[0]), "r"(a[1]), "r"(a[2]), "r"(a[3]), "r"(b[0]), "r"(b[1]));
}

// ---------------- tiling ------------------------------------------------------
#define BM 128
#define BN 128
#define BK 64
#define LDT 72                               // padded row stride (elems) = 144 B
#define TILE_BYTES (128 * LDT * 2)           // 18432
#define OFF_B TILE_BYTES
#define STAGE (TILE_BYTES * 2)               // 36864
#define NST 3
#define SMEM_TOT (NST * STAGE)               // 110592

// fill one 128 x 64 fp16 tile: 1024 x 16B chunks, 4 per thread
template <typename T>
__device__ __forceinline__ void load_tile(uint32_t dst, const T* __restrict__ src,
                                          int k0, int K, int tid) {
#pragma unroll
    for (int i = 0; i < 4; i++) {
        int op = tid + i * 256;
        int row = op >> 3, c = op & 7;
        uint32_t off = (uint32_t)(row * LDT + c * 8) * 2;
        cp16(dst + off, src + (size_t)row * K + k0 + c * 8);
    }
}

// ============================================================================
// Generic fp16 single x single GEMM: C[Mg,Ntot] = A[Mg,K] @ B[Ntot,K]^T
// ============================================================================
template <typename OutT>
__global__ void __launch_bounds__(256, 2)
gemm_fp16_kernel(const __half* __restrict__ A, const __half* __restrict__ B,
                 OutT* __restrict__ C, int K, int Mg, int Ntot) {
    extern __shared__ char smem[];
    const uint32_t sbase = smem_u32(smem);
    const int tid = threadIdx.x, wid = tid >> 5, lid = tid & 31;
    const int g = blockIdx.z;
    const int mBase = blockIdx.y * BM, nBase = blockIdx.x * BN;

    const __half* a0 = A + (size_t)g * Mg * K + (size_t)mBase * K;
    const __half* b0 = B + (size_t)g * Ntot * K + (size_t)nBase * K;
    OutT* c = C + (size_t)g * Mg * Ntot + (size_t)mBase * Ntot + nBase;

    // 2 (m) x 4 (n) warps; warp tile 64 x 32
    const int wm = (wid >> 2) * 64, wn = (wid & 3) * 32;
    const int lr = lid & 7, ls = lid >> 3;
    // A ldmatrix.x4 lane mapping (m16k16: 2 row-halves x 2 k-halves)
    const uint32_t aRow = (uint32_t)((ls & 1) * 8 + lr);
    const uint32_t aK   = (uint32_t)((ls >> 1) * 8);
    // B paired ldmatrix.x4 lane mapping: groups = (nt k0),(nt k8),(nt+1 k0),(nt+1 k8)
    const uint32_t bRow = (uint32_t)(((lid >> 4) & 1) * 8 + lr);
    const uint32_t bK   = (uint32_t)(((lid >> 3) & 1) * 8);

    float acc[4][4][4];
#pragma unroll
    for (int mt = 0; mt < 4; mt++)
#pragma unroll
        for (int nt = 0; nt < 4; nt++)
#pragma unroll
            for (int q = 0; q < 4; q++) acc[mt][nt][q] = 0.f;

    const int nk = K / BK;
    // prologue: fill stages 0..NST-2
#pragma unroll
    for (int p = 0; p < NST - 1; p++) {
        const uint32_t st = sbase + (uint32_t)p * STAGE;
        load_tile(st,         a0, p * BK, K, tid);
        load_tile(st + OFF_B, b0, p * BK, K, tid);
        CP_COMMIT();
    }

    int sIdx = 0;
    for (int it = 0; it < nk; ++it) {
        if (it + NST - 1 < nk) {
            int s2 = sIdx + NST - 1; if (s2 >= NST) s2 -= NST;
            const uint32_t st2 = sbase + (uint32_t)s2 * STAGE;
            const int k2 = (it + NST - 1) * BK;
            load_tile(st2,         a0, k2, K, tid);
            load_tile(st2 + OFF_B, b0, k2, K, tid);
        }
        CP_COMMIT();
        CP_WAIT(NST - 1);
        __syncthreads();

        const uint32_t st = sbase + (uint32_t)sIdx * STAGE;
#pragma unroll
        for (int kk = 0; kk < BK; kk += 16) {
            // B: 2 paired x4 loads cover nt=0..3 (both k-halves)
            uint32_t bf[4][2];
#pragma unroll
            for (int p = 0; p < 2; p++) {
                uint32_t r[4];
                uint32_t ro = (uint32_t)((wn + p * 16 + bRow) * LDT + kk + bK) * 2;
                ldsm_x4(r, st + OFF_B + ro);
                bf[p * 2 + 0][0] = r[0]; bf[p * 2 + 0][1] = r[1];
                bf[p * 2 + 1][0] = r[2]; bf[p * 2 + 1][1] = r[3];
            }
#pragma unroll
            for (int mt = 0; mt < 4; mt++) {
                uint32_t a[4];
                uint32_t ro = (uint32_t)((wm + mt * 16 + aRow) * LDT + kk + aK) * 2;
                ldsm_x4(a, st + ro);
#pragma unroll
                for (int nt = 0; nt < 4; nt++)
                    mma_fp16(acc[mt][nt], a, bf[nt]);
            }
        }
        __syncthreads();
        if (++sIdx == NST) sIdx = 0;
    }

    // epilogue
    const int er = lid >> 2, ec = (lid & 3) * 2;
#pragma unroll
    for (int mt = 0; mt < 4; mt++)
#pragma unroll
        for (int nt = 0; nt < 4; nt++) {
            int row = wm + mt * 16 + er, col = wn + nt * 8 + ec;
            if constexpr (sizeof(OutT) == 4) {
                *(float2*)&c[(size_t)row * Ntot + col] =
                    make_float2(acc[mt][nt][0], acc[mt][nt][1]);
                *(float2*)&c[(size_t)(row + 8) * Ntot + col] =
                    make_float2(acc[mt][nt][2], acc[mt][nt][3]);
            } else {
                __half2 v01 = __floats2half2_rn(acc[mt][nt][0], acc[mt][nt][1]);
                __half2 v23 = __floats2half2_rn(acc[mt][nt][2], acc[mt][nt][3]);
                *(uint32_t*)&c[(size_t)row * Ntot + col] = *(uint32_t*)&v01;
                *(uint32_t*)&c[(size_t)(row + 8) * Ntot + col] = *(uint32_t*)&v23;
            }
        }
}

// ---------------- helper kernels --------------------------------------------
// fused fold + transpose + fp16 convert:
// WeffT[g][o][c] = fp16( 64 * sum_r Wo[g][(kv*4+r)*64+d][o] ),  c = kv*64+d
__global__ void fold_transpose_kernel(const float* __restrict__ Wo,
                                      __half* __restrict__ out) {
    __shared__ float t[32][33];
    const int g = blockIdx.z;
    const int oB = blockIdx.x * 32;
    const int cB = blockIdx.y * 32;
    const int tx = threadIdx.x, ty = threadIdx.y;   // 32 x 8
    const float* wo = Wo + (size_t)g * NEMB * NEMB;
#pragma unroll
    for (int j = 0; j < 4; j++) {
        int cc = cB + ty + j * 8;
        int kv = cc >> 6, d = cc & 63;
        int o = oB + tx;
        float s = 0.f;
#pragma unroll
        for (int r = 0; r < NRAT; r++)
            s += wo[(size_t)((kv * NRAT + r) * NHD + d) * NEMB + o];
        t[ty + j * 8][tx] = 64.0f * s;
    }
    __syncthreads();
    __half* O = out + (size_t)g * NEMB * KVDIM;
#pragma unroll
    for (int j = 0; j < 4; j++) {
        float x = t[tx][ty + j * 8];
        O[(size_t)(oB + ty + j * 8) * KVDIM + cB + tx] = __float2half_rn(x);
    }
}

// fp32 -> fp16 convert, float4-vectorized
__global__ void convert_half_kernel(const float* __restrict__ in,
                                    __half* __restrict__ out, size_t n4) {
    size_t i = (size_t)blockIdx.x * blockDim.x + threadIdx.x;
    if (i >= n4) return;
    float4 v = ((const float4*)in)[i];
    __half2 h01 = __floats2half2_rn(v.x, v.y);
    __half2 h23 = __floats2half2_rn(v.z, v.w);
    uint2 o;
    o.x = *(uint32_t*)&h01; o.y = *(uint32_t*)&h23;
    ((uint2*)out)[i] = o;
}

// ---------------- launch -----------------------------------------------------
extern "C" void kernel_launch(void* const* d_in, const int* in_sizes, int n_in,
                              void* d_out, int out_size) {
    const float* tensor = (const float*)d_in[0];
    const float* Wv = (const float*)d_in[3];
    const float* Wo = (const float*)d_in[4];
    float* out = (float*)d_out;

    cudaFuncSetAttribute(gemm_fp16_kernel<float>,
                         cudaFuncAttributeMaxDynamicSharedMemorySize, SMEM_TOT);
    cudaFuncSetAttribute(gemm_fp16_kernel<__half>,
                         cudaFuncAttributeMaxDynamicSharedMemorySize, SMEM_TOT);

    __half *wt, *wvh, *bh, *xh;
    cudaGetSymbolAddress((void**)&wt,  g_wt);
    cudaGetSymbolAddress((void**)&wvh, g_wvh);
    cudaGetSymbolAddress((void**)&bh,  g_bh);
    cudaGetSymbolAddress((void**)&xh,  g_xh);

    // 1. fold+transpose: Wo -> WeffT fp16 [g][1024][256]
    {
        dim3 grid(NEMB / 32, KVDIM / 32, NG);
        fold_transpose_kernel<<<grid, dim3(32, 8)>>>(Wo, wt);
    }
    // 2. Wv -> fp16 [g][1024][256]
    {
        size_t n4 = (size_t)NG * NEMB * KVDIM / 4;
        convert_half_kernel<<<(unsigned)((n4 + 255) / 256), 256>>>(Wv, wvh, n4);
    }
    // 3. GEMM2: WcombT[o][m] = sum_c WeffT[o][c] * Wv[m][c]  (K=256, fp16 out)
    {
        dim3 grid(NEMB / BN, NEMB / BM, NG);
        gemm_fp16_kernel<__half><<<grid, 256, SMEM_TOT>>>(wt, wvh, bh,
                                                          KVDIM, NEMB, NEMB);
    }
    // 4. X -> fp16
    {
        size_t n4 = (size_t)NG * MROWS * NEMB / 4;
        convert_half_kernel<<<(unsigned)((n4 + 255) / 256), 256>>>(tensor, xh, n4);
    }
    // 5. GEMM3: out = X @ Wcomb  (K=1024, fp32 out)
    {
        dim3 grid(NEMB / BN, MROWS / BM, NG);
        gemm_fp16_kernel<float><<<grid, 256, SMEM_TOT>>>(xh, bh, out,
                                                         NEMB, MROWS, NEMB);
    }
}

// round 9
// speedup vs baseline: 9.3275x; 1.5505x over previous
#include <cuda_runtime.h>
#include <cuda_fp16.h>
#include <cstdint>

// ============================================================================
// GroupedMultiQueryAttention — full algebraic reduction, low-rank factored.
//
// attention = 64 * v (softmax rows sum to 1; q,k summed out)  =>
//   out[g] = X[g] @ Wv[g] @ Weff[g]        (Weff = 64 * head-folded Wo)
// Round 9: do NOT materialize Wcomb (rank-256!). Two thin GEMMs instead:
//   GEMM-a: Y = X @ Wv        (M=4096/g, N=256, K=1024)  fp16-out fused
//   GEMM-b: out = Y @ Weff    (M=4096/g, N=1024, K=256)  fp32-out
// 34.4 GF total vs 73 GF before. fp16 single x single HMMA throughout.
// ============================================================================

#define NG    8
#define NEMB  1024
#define KVDIM 256
#define MROWS 4096
#define NRAT  4
#define NHD   64

// ---------------- static device scratch -------------------------------------
__device__ __half g_wt  [NG * NEMB * KVDIM];          // WeffT fp16 [g][o=1024][c=256]
__device__ __half g_wvt [NG * KVDIM * NEMB];          // WvT  fp16 [g][c=256][i=1024]
__device__ __half g_xh  [(size_t)NG * MROWS * NEMB];  // X fp16    [g][m][i]
__device__ __half g_y   [NG * MROWS * KVDIM];         // Y fp16    [g][m][c]

// ---------------- PTX helpers ------------------------------------------------
__device__ __forceinline__ uint32_t smem_u32(const void* p) {
    uint32_t a;
    asm("{ .reg .u64 t; cvta.to.shared.u64 t, %1; cvt.u32.u64 %0, t; }" : "=r"(a) : "l"(p));
    return a;
}
__device__ __forceinline__ void cp16(uint32_t dst, const void* src) {
    asm volatile("cp.async.cg.shared.global [%0], [%1], 16;" :: "r"(dst), "l"(src));
}
#define CP_COMMIT() asm volatile("cp.async.commit_group;" ::: "memory")
#define CP_WAIT(n)  asm volatile("cp.async.wait_group %0;" :: "n"(n) : "memory")

__device__ __forceinline__ void ldsm_x4(uint32_t* r, uint32_t addr) {
    asm volatile("ldmatrix.sync.aligned.m8n8.x4.shared.b16 {%0,%1,%2,%3}, [%4];"
                 : "=r"(r[0]), "=r"(r[1]), "=r"(r[2]), "=r"(r[3]) : "r"(addr));
}
__device__ __forceinline__ void mma_fp16(float* d, const uint32_t* a, const uint32_t* b) {
    asm volatile("mma.sync.aligned.m16n8k16.row.col.f32.f16.f16.f32 "
                 "{%0,%1,%2,%3}, {%4,%5,%6,%7}, {%8,%9}, {%0,%1,%2,%3};"
                 : "+f"(d[0]), "+f"(d[1]), "+f"(d[2]), "+f"(d[3])
                 : "r"(a[0]), "r"(a[1]), "r"(a[2]), "r"(a[3]), "r"(b[0]), "r"(b[1]));
}

// ---------------- tiling ------------------------------------------------------
#define BM 128
#define BN 128
#define BK 64
#define LDT 72                               // padded row stride (elems) = 144 B
#define TILE_BYTES (128 * LDT * 2)           // 18432
#define OFF_B TILE_BYTES
#define STAGE (TILE_BYTES * 2)               // 36864
#define NST 3
#define SMEM_TOT (NST * STAGE)               // 110592

template <typename T>
__device__ __forceinline__ void load_tile(uint32_t dst, const T* __restrict__ src,
                                          int k0, int K, int tid) {
#pragma unroll
    for (int i = 0; i < 4; i++) {
        int op = tid + i * 256;
        int row = op >> 3, c = op & 7;
        uint32_t off = (uint32_t)(row * LDT + c * 8) * 2;
        cp16(dst + off, src + (size_t)row * K + k0 + c * 8);
    }
}

// ============================================================================
// Generic fp16 single x single GEMM: C[Mg,Ntot] = A[Mg,K] @ B[Ntot,K]^T
// ============================================================================
template <typename OutT>
__global__ void __launch_bounds__(256, 2)
gemm_fp16_kernel(const __half* __restrict__ A, const __half* __restrict__ B,
                 OutT* __restrict__ C, int K, int Mg, int Ntot) {
    extern __shared__ char smem[];
    const uint32_t sbase = smem_u32(smem);
    const int tid = threadIdx.x, wid = tid >> 5, lid = tid & 31;
    const int g = blockIdx.z;
    const int mBase = blockIdx.y * BM, nBase = blockIdx.x * BN;

    const __half* a0 = A + (size_t)g * Mg * K + (size_t)mBase * K;
    const __half* b0 = B + (size_t)g * Ntot * K + (size_t)nBase * K;
    OutT* c = C + (size_t)g * Mg * Ntot + (size_t)mBase * Ntot + nBase;

    const int wm = (wid >> 2) * 64, wn = (wid & 3) * 32;
    const int lr = lid & 7, ls = lid >> 3;
    const uint32_t aRow = (uint32_t)((ls & 1) * 8 + lr);
    const uint32_t aK   = (uint32_t)((ls >> 1) * 8);
    const uint32_t bRow = (uint32_t)(((lid >> 4) & 1) * 8 + lr);
    const uint32_t bK   = (uint32_t)(((lid >> 3) & 1) * 8);

    float acc[4][4][4];
#pragma unroll
    for (int mt = 0; mt < 4; mt++)
#pragma unroll
        for (int nt = 0; nt < 4; nt++)
#pragma unroll
            for (int q = 0; q < 4; q++) acc[mt][nt][q] = 0.f;

    const int nk = K / BK;
#pragma unroll
    for (int p = 0; p < NST - 1; p++) {
        if (p < nk) {
            const uint32_t st = sbase + (uint32_t)p * STAGE;
            load_tile(st,         a0, p * BK, K, tid);
            load_tile(st + OFF_B, b0, p * BK, K, tid);
        }
        CP_COMMIT();
    }

    int sIdx = 0;
    for (int it = 0; it < nk; ++it) {
        if (it + NST - 1 < nk) {
            int s2 = sIdx + NST - 1; if (s2 >= NST) s2 -= NST;
            const uint32_t st2 = sbase + (uint32_t)s2 * STAGE;
            const int k2 = (it + NST - 1) * BK;
            load_tile(st2,         a0, k2, K, tid);
            load_tile(st2 + OFF_B, b0, k2, K, tid);
        }
        CP_COMMIT();
        CP_WAIT(NST - 1);
        __syncthreads();

        const uint32_t st = sbase + (uint32_t)sIdx * STAGE;
#pragma unroll
        for (int kk = 0; kk < BK; kk += 16) {
            uint32_t bf[4][2];
#pragma unroll
            for (int p = 0; p < 2; p++) {
                uint32_t r[4];
                uint32_t ro = (uint32_t)((wn + p * 16 + bRow) * LDT + kk + bK) * 2;
                ldsm_x4(r, st + OFF_B + ro);
                bf[p * 2 + 0][0] = r[0]; bf[p * 2 + 0][1] = r[1];
                bf[p * 2 + 1][0] = r[2]; bf[p * 2 + 1][1] = r[3];
            }
#pragma unroll
            for (int mt = 0; mt < 4; mt++) {
                uint32_t a[4];
                uint32_t ro = (uint32_t)((wm + mt * 16 + aRow) * LDT + kk + aK) * 2;
                ldsm_x4(a, st + ro);
#pragma unroll
                for (int nt = 0; nt < 4; nt++)
                    mma_fp16(acc[mt][nt], a, bf[nt]);
            }
        }
        __syncthreads();
        if (++sIdx == NST) sIdx = 0;
    }

    const int er = lid >> 2, ec = (lid & 3) * 2;
#pragma unroll
    for (int mt = 0; mt < 4; mt++)
#pragma unroll
        for (int nt = 0; nt < 4; nt++) {
            int row = wm + mt * 16 + er, col = wn + nt * 8 + ec;
            if constexpr (sizeof(OutT) == 4) {
                *(float2*)&c[(size_t)row * Ntot + col] =
                    make_float2(acc[mt][nt][0], acc[mt][nt][1]);
                *(float2*)&c[(size_t)(row + 8) * Ntot + col] =
                    make_float2(acc[mt][nt][2], acc[mt][nt][3]);
            } else {
                __half2 v01 = __floats2half2_rn(acc[mt][nt][0], acc[mt][nt][1]);
                __half2 v23 = __floats2half2_rn(acc[mt][nt][2], acc[mt][nt][3]);
                *(uint32_t*)&c[(size_t)row * Ntot + col] = *(uint32_t*)&v01;
                *(uint32_t*)&c[(size_t)(row + 8) * Ntot + col] = *(uint32_t*)&v23;
            }
        }
}

// ---------------- helper kernels --------------------------------------------
// fused fold + transpose + fp16:
// WeffT[g][o][c] = fp16( 64 * sum_r Wo[g][(kv*4+r)*64+d][o] ),  c = kv*64+d
__global__ void fold_transpose_kernel(const float* __restrict__ Wo,
                                      __half* __restrict__ out) {
    __shared__ float t[32][33];
    const int g = blockIdx.z;
    const int oB = blockIdx.x * 32;
    const int cB = blockIdx.y * 32;
    const int tx = threadIdx.x, ty = threadIdx.y;   // 32 x 8
    const float* wo = Wo + (size_t)g * NEMB * NEMB;
#pragma unroll
    for (int j = 0; j < 4; j++) {
        int cc = cB + ty + j * 8;
        int kv = cc >> 6, d = cc & 63;
        int o = oB + tx;
        float s = 0.f;
#pragma unroll
        for (int r = 0; r < NRAT; r++)
            s += wo[(size_t)((kv * NRAT + r) * NHD + d) * NEMB + o];
        t[ty + j * 8][tx] = 64.0f * s;
    }
    __syncthreads();
    __half* O = out + (size_t)g * NEMB * KVDIM;
#pragma unroll
    for (int j = 0; j < 4; j++) {
        float x = t[tx][ty + j * 8];
        O[(size_t)(oB + ty + j * 8) * KVDIM + cB + tx] = __float2half_rn(x);
    }
}

// transpose + fp16: in fp32 [R][C] -> out fp16 [C][R]  (per genome)
__global__ void transpose_half_kernel(const float* __restrict__ in,
                                      __half* __restrict__ out, int R, int Cc) {
    __shared__ float t[32][33];
    const int g = blockIdx.z;
    const int cB = blockIdx.x * 32, rB = blockIdx.y * 32;
    const int tx = threadIdx.x, ty = threadIdx.y;   // 32 x 8
    const float* I = in + (size_t)g * R * Cc;
#pragma unroll
    for (int j = 0; j < 4; j++)
        t[ty + j * 8][tx] = I[(size_t)(rB + ty + j * 8) * Cc + cB + tx];
    __syncthreads();
    __half* O = out + (size_t)g * R * Cc;
#pragma unroll
    for (int j = 0; j < 4; j++) {
        float x = t[tx][ty + j * 8];
        O[(size_t)(cB + ty + j * 8) * R + rB + tx] = __float2half_rn(x);
    }
}

// fp32 -> fp16 convert, float4-vectorized
__global__ void convert_half_kernel(const float* __restrict__ in,
                                    __half* __restrict__ out, size_t n4) {
    size_t i = (size_t)blockIdx.x * blockDim.x + threadIdx.x;
    if (i >= n4) return;
    float4 v = ((const float4*)in)[i];
    __half2 h01 = __floats2half2_rn(v.x, v.y);
    __half2 h23 = __floats2half2_rn(v.z, v.w);
    uint2 o;
    o.x = *(uint32_t*)&h01; o.y = *(uint32_t*)&h23;
    ((uint2*)out)[i] = o;
}

// ---------------- launch -----------------------------------------------------
extern "C" void kernel_launch(void* const* d_in, const int* in_sizes, int n_in,
                              void* d_out, int out_size) {
    const float* tensor = (const float*)d_in[0];
    const float* Wv = (const float*)d_in[3];
    const float* Wo = (const float*)d_in[4];
    float* out = (float*)d_out;

    cudaFuncSetAttribute(gemm_fp16_kernel<float>,
                         cudaFuncAttributeMaxDynamicSharedMemorySize, SMEM_TOT);
    cudaFuncSetAttribute(gemm_fp16_kernel<__half>,
                         cudaFuncAttributeMaxDynamicSharedMemorySize, SMEM_TOT);

    __half *wt, *wvt, *xh, *y;
    cudaGetSymbolAddress((void**)&wt,  g_wt);
    cudaGetSymbolAddress((void**)&wvt, g_wvt);
    cudaGetSymbolAddress((void**)&xh,  g_xh);
    cudaGetSymbolAddress((void**)&y,   g_y);

    // 1. fold+transpose: Wo -> WeffT fp16 [g][1024][256]
    {
        dim3 grid(NEMB / 32, KVDIM / 32, NG);
        fold_transpose_kernel<<<grid, dim3(32, 8)>>>(Wo, wt);
    }
    // 2. Wv [1024][256] -> WvT fp16 [256][1024]
    {
        dim3 grid(KVDIM / 32, NEMB / 32, NG);
        transpose_half_kernel<<<grid, dim3(32, 8)>>>(Wv, wvt, NEMB, KVDIM);
    }
    // 3. X -> fp16
    {
        size_t n4 = (size_t)NG * MROWS * NEMB / 4;
        convert_half_kernel<<<(unsigned)((n4 + 255) / 256), 256>>>(tensor, xh, n4);
    }
    // 4. GEMM-a: Y[m][c] = sum_i X[m][i] * WvT[c][i]   (K=1024, N=256, fp16 out)
    {
        dim3 grid(KVDIM / BN, MROWS / BM, NG);   // (2, 32, 8)
        gemm_fp16_kernel<__half><<<grid, 256, SMEM_TOT>>>(xh, wvt, y,
                                                          NEMB, MROWS, KVDIM);
    }
    // 5. GEMM-b: out[m][o] = sum_c Y[m][c] * WeffT[o][c]  (K=256, N=1024, fp32 out)
    {
        dim3 grid(NEMB / BN, MROWS / BM, NG);    // (8, 32, 8)
        gemm_fp16_kernel<float><<<grid, 256, SMEM_TOT>>>(y, wt, out,
                                                         KVDIM, MROWS, NEMB);
    }
}

// round 10
// speedup vs baseline: 10.1772x; 1.0911x over previous
#include <cuda_runtime.h>
#include <cuda_fp16.h>
#include <cstdint>

// ============================================================================
// GroupedMultiQueryAttention — full algebraic reduction, low-rank factored.
//
// attention = 64 * v (softmax rows sum to 1; q,k summed out)  =>
//   out[g] = X[g] @ Wv[g] @ Weff[g]        (Weff = 64 * head-folded Wo)
// GEMM-a: Y = X @ Wv    (M=4096/g, N=256, K=1024) — fp32 A ingested directly,
//   converted to fp16 in SMEM (kills the standalone convert kernel's 384 MB
//   of DRAM traffic). fp16-out fused.
// GEMM-b: out = Y @ Weff (M=4096/g, N=1024, K=256) — fp16 HMMA, fp32 out.
// ============================================================================

#define NG    8
#define NEMB  1024
#define KVDIM 256
#define MROWS 4096
#define NRAT  4
#define NHD   64

// ---------------- static device scratch -------------------------------------
__device__ __half g_wt  [NG * NEMB * KVDIM];   // WeffT fp16 [g][o=1024][c=256]
__device__ __half g_wvt [NG * KVDIM * NEMB];   // WvT  fp16 [g][c=256][i=1024]
__device__ __half g_y   [NG * MROWS * KVDIM];  // Y fp16    [g][m][c]

// ---------------- PTX helpers ------------------------------------------------
__device__ __forceinline__ uint32_t smem_u32(const void* p) {
    uint32_t a;
    asm("{ .reg .u64 t; cvta.to.shared.u64 t, %1; cvt.u32.u64 %0, t; }" : "=r"(a) : "l"(p));
    return a;
}
__device__ __forceinline__ void cp16(uint32_t dst, const void* src) {
    asm volatile("cp.async.cg.shared.global [%0], [%1], 16;" :: "r"(dst), "l"(src));
}
#define CP_COMMIT() asm volatile("cp.async.commit_group;" ::: "memory")
#define CP_WAIT(n)  asm volatile("cp.async.wait_group %0;" :: "n"(n) : "memory")

__device__ __forceinline__ void ldsm_x4(uint32_t* r, uint32_t addr) {
    asm volatile("ldmatrix.sync.aligned.m8n8.x4.shared.b16 {%0,%1,%2,%3}, [%4];"
                 : "=r"(r[0]), "=r"(r[1]), "=r"(r[2]), "=r"(r[3]) : "r"(addr));
}
__device__ __forceinline__ void mma_fp16(float* d, const uint32_t* a, const uint32_t* b) {
    asm volatile("mma.sync.aligned.m16n8k16.row.col.f32.f16.f16.f32 "
                 "{%0,%1,%2,%3}, {%4,%5,%6,%7}, {%8,%9}, {%0,%1,%2,%3};"
                 : "+f"(d[0]), "+f"(d[1]), "+f"(d[2]), "+f"(d[3])
                 : "r"(a[0]), "r"(a[1]), "r"(a[2]), "r"(a[3]), "r"(b[0]), "r"(b[1]));
}

// ============================================================================
// GEMM-a (fused convert): Y[Mg,256] = fp16(X)[Mg,K] @ WvT[256,K]^T
// BK=32, 3-stage fp32-A + fp16-B ring, single fp16-A staging buffer.
// ============================================================================
#define XBK 32
#define LDTA32 36                            // fp32 A row stride (floats), 144 B
#define A32_STAGE (128 * LDTA32 * 4)         // 18432
#define LDTB 40                              // fp16 row stride (halfs), 80 B
#define B16_STAGE (128 * LDTB * 2)           // 10240
#define XNST 3
#define XOFF_B (XNST * A32_STAGE)            // 55296
#define XOFF_STG (XOFF_B + XNST * B16_STAGE) // 86016
#define XSMEM_TOT (XOFF_STG + B16_STAGE)     // 96256

__global__ void __launch_bounds__(256, 2)
gemm_xa_kernel(const float* __restrict__ X, const __half* __restrict__ B,
               __half* __restrict__ Y, int K, int Mg, int Ntot) {
    extern __shared__ char smem[];
    const uint32_t sbase = smem_u32(smem);
    const int tid = threadIdx.x, wid = tid >> 5, lid = tid & 31;
    const int g = blockIdx.z;
    const int mBase = blockIdx.y * 128, nBase = blockIdx.x * 128;

    const float*  a0 = X + (size_t)g * Mg * K + (size_t)mBase * K;
    const __half* b0 = B + (size_t)g * Ntot * K + (size_t)nBase * K;
    __half* c = Y + (size_t)g * Mg * Ntot + (size_t)mBase * Ntot + nBase;

    const int wm = (wid >> 2) * 64, wn = (wid & 3) * 32;
    const int lr = lid & 7, ls = lid >> 3;
    const uint32_t aRow = (uint32_t)((ls & 1) * 8 + lr);
    const uint32_t aK   = (uint32_t)((ls >> 1) * 8);
    const uint32_t bRow = (uint32_t)(((lid >> 4) & 1) * 8 + lr);
    const uint32_t bK   = (uint32_t)(((lid >> 3) & 1) * 8);

    // convert-phase mapping: warp covers 32 consecutive rows of one k-half
    const int cvRow  = tid & 127;            // 0..127
    const int cvHalf = tid >> 7;             // 0..1  (k-half: 16 floats each)

    float acc[4][4][4];
#pragma unroll
    for (int mt = 0; mt < 4; mt++)
#pragma unroll
        for (int nt = 0; nt < 4; nt++)
#pragma unroll
            for (int q = 0; q < 4; q++) acc[mt][nt][q] = 0.f;

    const int nk = K / XBK;                  // 32
    // producers: A fp32 128x32 (1024 x 16B), B fp16 128x32 (512 x 16B)
    auto load_stage = [&](int s, int k0) {
        const uint32_t a32 = sbase + (uint32_t)s * A32_STAGE;
        const uint32_t b16 = sbase + XOFF_B + (uint32_t)s * B16_STAGE;
#pragma unroll
        for (int i = 0; i < 4; i++) {
            int op = tid + i * 256, row = op >> 3, cc = op & 7;
            cp16(a32 + (uint32_t)(row * LDTA32 + cc * 4) * 4,
                 a0 + (size_t)row * K + k0 + cc * 4);
        }
#pragma unroll
        for (int i = 0; i < 2; i++) {
            int op = tid + i * 256, row = op >> 2, cc = op & 3;
            cp16(b16 + (uint32_t)(row * LDTB + cc * 8) * 2,
                 b0 + (size_t)row * K + k0 + cc * 8);
        }
    };

#pragma unroll
    for (int p = 0; p < XNST - 1; p++) { load_stage(p, p * XBK); CP_COMMIT(); }

    const uint32_t stg = sbase + XOFF_STG;
    int sIdx = 0;
    for (int it = 0; it < nk; ++it) {
        if (it + XNST - 1 < nk) {
            int s2 = sIdx + XNST - 1; if (s2 >= XNST) s2 -= XNST;
            load_stage(s2, (it + XNST - 1) * XBK);
        }
        CP_COMMIT();
        CP_WAIT(XNST - 1);
        __syncthreads();

        // in-smem convert: A32[sIdx] -> fp16 staging (identical __float2half_rn)
        {
            const uint32_t a32 = sbase + (uint32_t)sIdx * A32_STAGE
                               + (uint32_t)(cvRow * LDTA32 + cvHalf * 16) * 4;
            const uint32_t d16 = stg + (uint32_t)(cvRow * LDTB + cvHalf * 16) * 2;
            uint32_t h[8];
#pragma unroll
            for (int j = 0; j < 4; j++) {
                float4 v;
                asm volatile("ld.shared.v4.f32 {%0,%1,%2,%3}, [%4];"
                             : "=f"(v.x), "=f"(v.y), "=f"(v.z), "=f"(v.w)
                             : "r"(a32 + j * 16));
                __half2 p0 = __floats2half2_rn(v.x, v.y);
                __half2 p1 = __floats2half2_rn(v.z, v.w);
                h[j * 2 + 0] = *(uint32_t*)&p0;
                h[j * 2 + 1] = *(uint32_t*)&p1;
            }
            asm volatile("st.shared.v4.b32 [%0], {%1,%2,%3,%4};"
                         :: "r"(d16), "r"(h[0]), "r"(h[1]), "r"(h[2]), "r"(h[3]));
            asm volatile("st.shared.v4.b32 [%0], {%1,%2,%3,%4};"
                         :: "r"(d16 + 16), "r"(h[4]), "r"(h[5]), "r"(h[6]), "r"(h[7]));
        }
        __syncthreads();

        const uint32_t bst = sbase + XOFF_B + (uint32_t)sIdx * B16_STAGE;
#pragma unroll
        for (int kk = 0; kk < XBK; kk += 16) {
            uint32_t bf[4][2];
#pragma unroll
            for (int p = 0; p < 2; p++) {
                uint32_t r[4];
                uint32_t ro = (uint32_t)((wn + p * 16 + bRow) * LDTB + kk + bK) * 2;
                ldsm_x4(r, bst + ro);
                bf[p * 2 + 0][0] = r[0]; bf[p * 2 + 0][1] = r[1];
                bf[p * 2 + 1][0] = r[2]; bf[p * 2 + 1][1] = r[3];
            }
#pragma unroll
            for (int mt = 0; mt < 4; mt++) {
                uint32_t a[4];
                uint32_t ro = (uint32_t)((wm + mt * 16 + aRow) * LDTB + kk + aK) * 2;
                ldsm_x4(a, stg + ro);
#pragma unroll
                for (int nt = 0; nt < 4; nt++)
                    mma_fp16(acc[mt][nt], a, bf[nt]);
            }
        }
        __syncthreads();
        if (++sIdx == XNST) sIdx = 0;
    }

    const int er = lid >> 2, ec = (lid & 3) * 2;
#pragma unroll
    for (int mt = 0; mt < 4; mt++)
#pragma unroll
        for (int nt = 0; nt < 4; nt++) {
            int row = wm + mt * 16 + er, col = wn + nt * 8 + ec;
            __half2 v01 = __floats2half2_rn(acc[mt][nt][0], acc[mt][nt][1]);
            __half2 v23 = __floats2half2_rn(acc[mt][nt][2], acc[mt][nt][3]);
            *(uint32_t*)&c[(size_t)row * Ntot + col] = *(uint32_t*)&v01;
            *(uint32_t*)&c[(size_t)(row + 8) * Ntot + col] = *(uint32_t*)&v23;
        }
}

// ============================================================================
// GEMM-b: out[Mg,1024] = Y[Mg,256] @ WeffT[1024,256]^T — fp16 HMMA, fp32 out
// BK=64, 3-stage ring (round-9 kernel).
// ============================================================================
#define BM 128
#define BN 128
#define BK 64
#define LDT 72
#define TILE_BYTES (128 * LDT * 2)           // 18432
#define OFF_B TILE_BYTES
#define STAGE (TILE_BYTES * 2)               // 36864
#define NST 3
#define SMEM_TOT (NST * STAGE)               // 110592

template <typename T>
__device__ __forceinline__ void load_tile(uint32_t dst, const T* __restrict__ src,
                                          int k0, int K, int tid) {
#pragma unroll
    for (int i = 0; i < 4; i++) {
        int op = tid + i * 256;
        int row = op >> 3, c = op & 7;
        uint32_t off = (uint32_t)(row * LDT + c * 8) * 2;
        cp16(dst + off, src + (size_t)row * K + k0 + c * 8);
    }
}

__global__ void __launch_bounds__(256, 2)
gemm_b_kernel(const __half* __restrict__ A, const __half* __restrict__ B,
              float* __restrict__ C, int K, int Mg, int Ntot) {
    extern __shared__ char smem[];
    const uint32_t sbase = smem_u32(smem);
    const int tid = threadIdx.x, wid = tid >> 5, lid = tid & 31;
    const int g = blockIdx.z;
    const int mBase = blockIdx.y * BM, nBase = blockIdx.x * BN;

    const __half* a0 = A + (size_t)g * Mg * K + (size_t)mBase * K;
    const __half* b0 = B + (size_t)g * Ntot * K + (size_t)nBase * K;
    float* c = C + (size_t)g * Mg * Ntot + (size_t)mBase * Ntot + nBase;

    const int wm = (wid >> 2) * 64, wn = (wid & 3) * 32;
    const int lr = lid & 7, ls = lid >> 3;
    const uint32_t aRow = (uint32_t)((ls & 1) * 8 + lr);
    const uint32_t aK   = (uint32_t)((ls >> 1) * 8);
    const uint32_t bRow = (uint32_t)(((lid >> 4) & 1) * 8 + lr);
    const uint32_t bK   = (uint32_t)(((lid >> 3) & 1) * 8);

    float acc[4][4][4];
#pragma unroll
    for (int mt = 0; mt < 4; mt++)
#pragma unroll
        for (int nt = 0; nt < 4; nt++)
#pragma unroll
            for (int q = 0; q < 4; q++) acc[mt][nt][q] = 0.f;

    const int nk = K / BK;                   // 4 for K=256
#pragma unroll
    for (int p = 0; p < NST - 1; p++) {
        if (p < nk) {
            const uint32_t st = sbase + (uint32_t)p * STAGE;
            load_tile(st,         a0, p * BK, K, tid);
            load_tile(st + OFF_B, b0, p * BK, K, tid);
        }
        CP_COMMIT();
    }

    int sIdx = 0;
    for (int it = 0; it < nk; ++it) {
        if (it + NST - 1 < nk) {
            int s2 = sIdx + NST - 1; if (s2 >= NST) s2 -= NST;
            const uint32_t st2 = sbase + (uint32_t)s2 * STAGE;
            const int k2 = (it + NST - 1) * BK;
            load_tile(st2,         a0, k2, K, tid);
            load_tile(st2 + OFF_B, b0, k2, K, tid);
        }
        CP_COMMIT();
        CP_WAIT(NST - 1);
        __syncthreads();

        const uint32_t st = sbase + (uint32_t)sIdx * STAGE;
#pragma unroll
        for (int kk = 0; kk < BK; kk += 16) {
            uint32_t bf[4][2];
#pragma unroll
            for (int p = 0; p < 2; p++) {
                uint32_t r[4];
                uint32_t ro = (uint32_t)((wn + p * 16 + bRow) * LDT + kk + bK) * 2;
                ldsm_x4(r, st + OFF_B + ro);
                bf[p * 2 + 0][0] = r[0]; bf[p * 2 + 0][1] = r[1];
                bf[p * 2 + 1][0] = r[2]; bf[p * 2 + 1][1] = r[3];
            }
#pragma unroll
            for (int mt = 0; mt < 4; mt++) {
                uint32_t a[4];
                uint32_t ro = (uint32_t)((wm + mt * 16 + aRow) * LDT + kk + aK) * 2;
                ldsm_x4(a, st + ro);
#pragma unroll
                for (int nt = 0; nt < 4; nt++)
                    mma_fp16(acc[mt][nt], a, bf[nt]);
            }
        }
        __syncthreads();
        if (++sIdx == NST) sIdx = 0;
    }

    const int er = lid >> 2, ec = (lid & 3) * 2;
#pragma unroll
    for (int mt = 0; mt < 4; mt++)
#pragma unroll
        for (int nt = 0; nt < 4; nt++) {
            int row = wm + mt * 16 + er, col = wn + nt * 8 + ec;
            *(float2*)&c[(size_t)row * Ntot + col] =
                make_float2(acc[mt][nt][0], acc[mt][nt][1]);
            *(float2*)&c[(size_t)(row + 8) * Ntot + col] =
                make_float2(acc[mt][nt][2], acc[mt][nt][3]);
        }
}

// ---------------- helper kernels --------------------------------------------
// fused fold + transpose + fp16:
// WeffT[g][o][c] = fp16( 64 * sum_r Wo[g][(kv*4+r)*64+d][o] ),  c = kv*64+d
__global__ void fold_transpose_kernel(const float* __restrict__ Wo,
                                      __half* __restrict__ out) {
    __shared__ float t[32][33];
    const int g = blockIdx.z;
    const int oB = blockIdx.x * 32;
    const int cB = blockIdx.y * 32;
    const int tx = threadIdx.x, ty = threadIdx.y;   // 32 x 8
    const float* wo = Wo + (size_t)g * NEMB * NEMB;
#pragma unroll
    for (int j = 0; j < 4; j++) {
        int cc = cB + ty + j * 8;
        int kv = cc >> 6, d = cc & 63;
        int o = oB + tx;
        float s = 0.f;
#pragma unroll
        for (int r = 0; r < NRAT; r++)
            s += wo[(size_t)((kv * NRAT + r) * NHD + d) * NEMB + o];
        t[ty + j * 8][tx] = 64.0f * s;
    }
    __syncthreads();
    __half* O = out + (size_t)g * NEMB * KVDIM;
#pragma unroll
    for (int j = 0; j < 4; j++) {
        float x = t[tx][ty + j * 8];
        O[(size_t)(oB + ty + j * 8) * KVDIM + cB + tx] = __float2half_rn(x);
    }
}

// transpose + fp16: in fp32 [R][C] -> out fp16 [C][R]  (per genome)
__global__ void transpose_half_kernel(const float* __restrict__ in,
                                      __half* __restrict__ out, int R, int Cc) {
    __shared__ float t[32][33];
    const int g = blockIdx.z;
    const int cB = blockIdx.x * 32, rB = blockIdx.y * 32;
    const int tx = threadIdx.x, ty = threadIdx.y;   // 32 x 8
    const float* I = in + (size_t)g * R * Cc;
#pragma unroll
    for (int j = 0; j < 4; j++)
        t[ty + j * 8][tx] = I[(size_t)(rB + ty + j * 8) * Cc + cB + tx];
    __syncthreads();
    __half* O = out + (size_t)g * R * Cc;
#pragma unroll
    for (int j = 0; j < 4; j++) {
        float x = t[tx][ty + j * 8];
        O[(size_t)(cB + ty + j * 8) * R + rB + tx] = __float2half_rn(x);
    }
}

// ---------------- launch -----------------------------------------------------
extern "C" void kernel_launch(void* const* d_in, const int* in_sizes, int n_in,
                              void* d_out, int out_size) {
    const float* tensor = (const float*)d_in[0];
    const float* Wv = (const float*)d_in[3];
    const float* Wo = (const float*)d_in[4];
    float* out = (float*)d_out;

    cudaFuncSetAttribute(gemm_xa_kernel,
                         cudaFuncAttributeMaxDynamicSharedMemorySize, XSMEM_TOT);
    cudaFuncSetAttribute(gemm_b_kernel,
                         cudaFuncAttributeMaxDynamicSharedMemorySize, SMEM_TOT);

    __half *wt, *wvt, *y;
    cudaGetSymbolAddress((void**)&wt,  g_wt);
    cudaGetSymbolAddress((void**)&wvt, g_wvt);
    cudaGetSymbolAddress((void**)&y,   g_y);

    // 1. fold+transpose: Wo -> WeffT fp16 [g][1024][256]
    {
        dim3 grid(NEMB / 32, KVDIM / 32, NG);
        fold_transpose_kernel<<<grid, dim3(32, 8)>>>(Wo, wt);
    }
    // 2. Wv [1024][256] -> WvT fp16 [256][1024]
    {
        dim3 grid(KVDIM / 32, NEMB / 32, NG);
        transpose_half_kernel<<<grid, dim3(32, 8)>>>(Wv, wvt, NEMB, KVDIM);
    }
    // 3. GEMM-a (fused convert): Y = fp16(X) @ WvT^T  (K=1024, N=256)
    {
        dim3 grid(KVDIM / 128, MROWS / 128, NG);   // (2, 32, 8)
        gemm_xa_kernel<<<grid, 256, XSMEM_TOT>>>(tensor, wvt, y,
                                                 NEMB, MROWS, KVDIM);
    }
    // 4. GEMM-b: out = Y @ WeffT^T  (K=256, N=1024, fp32 out)
    {
        dim3 grid(NEMB / BN, MROWS / BM, NG);      // (8, 32, 8)
        gemm_b_kernel<<<grid, 256, SMEM_TOT>>>(y, wt, out,
                                               KVDIM, MROWS, NEMB);
    }
}